// round 5
// baseline (speedup 1.0000x reference)
#include <cuda_runtime.h>
#include <cuda_bf16.h>
#include <math_constants.h>

// Problem constants
#define S_LEN 2048
#define HID   4096
#define NH    32
#define NKV   8
#define HD    128

// Scratch (static device globals; no allocation APIs used anywhere)
__device__ float g_Q[S_LEN * HID];   // Q after proj+rope, layout [s][h*128+d]
__device__ float g_O[S_LEN * HID];   // attention output, layout [s][h*128+d]

// ---------------- packed f32x2 helpers (Blackwell FFMA2 path) ----------------
__device__ __forceinline__ unsigned long long pack_dup(float x) {
    unsigned long long r; unsigned int u = __float_as_uint(x);
    asm("mov.b64 %0, {%1, %1};" : "=l"(r) : "r"(u));
    return r;
}
__device__ __forceinline__ void fma2(unsigned long long& d,
                                     unsigned long long a, unsigned long long b) {
    asm("fma.rn.f32x2 %0, %1, %2, %0;" : "+l"(d) : "l"(a), "l"(b));
}
__device__ __forceinline__ void mul2(unsigned long long& d, unsigned long long a) {
    asm("mul.rn.f32x2 %0, %1, %0;" : "+l"(d) : "l"(a));
}
__device__ __forceinline__ float lo32(unsigned long long v) {
    return __uint_as_float((unsigned int)(v & 0xffffffffull));
}
__device__ __forceinline__ float hi32(unsigned long long v) {
    return __uint_as_float((unsigned int)(v >> 32));
}

// ---------------- SGEMM: C[M,N] = A[M,K] @ B[K,N], all row-major fp32 --------
// 128x128 CTA tile, BK=16, 256 threads, 8x8 microtile with f32x2 accumulators.
__global__ __launch_bounds__(256)
void sgemm128(const float* __restrict__ A, const float* __restrict__ B,
              float* __restrict__ C, int M, int N, int K) {
    __shared__ float As[16][128];   // transposed: As[k][m]
    __shared__ float Bs[16][128];   // Bs[k][n]

    const int tid = threadIdx.x;
    const int bx = blockIdx.x;      // N tile
    const int by = blockIdx.y;      // M tile
    const int tx = tid & 15;        // -> 8 cols
    const int ty = tid >> 4;        // -> 8 rows

    const int arow = tid >> 2;           // 0..63
    const int ac   = (tid & 3) << 2;     // 0,4,8,12
    const int brow = tid >> 5;           // 0..7
    const int bc   = (tid & 31) << 2;    // 0..124

    const float* Aload = A + (size_t)(by * 128 + arow) * K + ac;
    const float* Bload = B + (size_t)brow * N + bx * 128 + bc;

    unsigned long long acc[8][4];
    #pragma unroll
    for (int i = 0; i < 8; i++)
        #pragma unroll
        for (int j = 0; j < 4; j++) acc[i][j] = 0ull;

    // prefetch tile 0
    float4 pa0 = *(const float4*)(Aload);
    float4 pa1 = *(const float4*)(Aload + (size_t)64 * K);
    float4 pb0 = *(const float4*)(Bload);
    float4 pb1 = *(const float4*)(Bload + (size_t)8 * N);

    for (int k0 = 0; k0 < K; k0 += 16) {
        __syncthreads();
        As[ac + 0][arow] = pa0.x; As[ac + 1][arow] = pa0.y;
        As[ac + 2][arow] = pa0.z; As[ac + 3][arow] = pa0.w;
        As[ac + 0][arow + 64] = pa1.x; As[ac + 1][arow + 64] = pa1.y;
        As[ac + 2][arow + 64] = pa1.z; As[ac + 3][arow + 64] = pa1.w;
        *(float4*)&Bs[brow][bc]     = pb0;
        *(float4*)&Bs[brow + 8][bc] = pb1;
        __syncthreads();

        if (k0 + 16 < K) {
            pa0 = *(const float4*)(Aload + (k0 + 16));
            pa1 = *(const float4*)(Aload + (size_t)64 * K + (k0 + 16));
            pb0 = *(const float4*)(Bload + (size_t)(k0 + 16) * N);
            pb1 = *(const float4*)(Bload + (size_t)(k0 + 24) * N);
        }

        #pragma unroll
        for (int kk = 0; kk < 16; kk++) {
            float4 a0 = *(const float4*)&As[kk][ty << 3];
            float4 a1 = *(const float4*)&As[kk][(ty << 3) + 4];
            const unsigned long long* bp =
                (const unsigned long long*)&Bs[kk][tx << 3];
            unsigned long long b0 = bp[0], b1 = bp[1], b2 = bp[2], b3 = bp[3];
            float am[8] = {a0.x, a0.y, a0.z, a0.w, a1.x, a1.y, a1.z, a1.w};
            #pragma unroll
            for (int i = 0; i < 8; i++) {
                unsigned long long ad = pack_dup(am[i]);
                fma2(acc[i][0], ad, b0);
                fma2(acc[i][1], ad, b1);
                fma2(acc[i][2], ad, b2);
                fma2(acc[i][3], ad, b3);
            }
        }
    }

    const int row0 = by * 128 + (ty << 3);
    const int col0 = bx * 128 + (tx << 3);
    #pragma unroll
    for (int i = 0; i < 8; i++) {
        float4 v0 = make_float4(lo32(acc[i][0]), hi32(acc[i][0]),
                                lo32(acc[i][1]), hi32(acc[i][1]));
        float4 v1 = make_float4(lo32(acc[i][2]), hi32(acc[i][2]),
                                lo32(acc[i][3]), hi32(acc[i][3]));
        float* cp = C + (size_t)(row0 + i) * N + col0;
        *(float4*)cp       = v0;
        *(float4*)(cp + 4) = v1;
    }
}

// ---------------- RoPE (in-place on g_Q) ------------------------------------
// out[:64] = x1*cos - x2*sin ; out[64:] = x2*cos + x1*sin ; angle = pos*theta^(-i/64)
__global__ void rope_kernel(float* __restrict__ Q, const int* __restrict__ pos) {
    int t = blockIdx.x * blockDim.x + threadIdx.x;   // S*NH*64 threads
    int i = t & 63;
    int h = (t >> 6) & 31;
    int s = t >> 11;
    // ln(10000)/64 = 0.14391156...
    float inv = expf(-(float)i * 0.14391156384599196f);
    float ang = (float)pos[s] * inv;
    float sn, cs;
    sincosf(ang, &sn, &cs);
    float* p = Q + (size_t)s * HID + h * HD + i;
    float x1 = p[0], x2 = p[64];
    p[0]  = x1 * cs - x2 * sn;
    p[64] = x2 * cs + x1 * sn;
}

// ---------------- Flash attention (causal, GQA) ------------------------------
// CTA = (query tile of 128 rows, head). KV tiles of 64 keys. fp32 + f32x2 FMA.
// Heaviest q-tiles scheduled first (causal work ∝ qt+1) for wave balance.
__global__ __launch_bounds__(256)
void attn_kernel(const float* __restrict__ Q, const float* __restrict__ Kc,
                 const float* __restrict__ Vc, float* __restrict__ O) {
    extern __shared__ float sm[];
    float* Qs  = sm;                 // [d][m]   128x128 (transposed)
    float* Ks  = Qs + 128 * 128;     // [d][n]   128x64  (transposed)
    float* Vs  = Ks + 128 * 64;      // [n][d]   64x128
    float* Ps  = Vs + 64 * 128;      // [n][m]   64x128  (transposed S/P tile)
    float* m_s = Ps + 64 * 128;      // [128]
    float* l_s = m_s + 128;          // [128]
    float* a_s = l_s + 128;          // [128] rescale factors

    const int tid = threadIdx.x;
    const int qt  = (int)gridDim.x - 1 - (int)blockIdx.x;  // heavy tiles first
    const int h   = blockIdx.y;      // 0..31
    const int r0  = qt * 128;
    const int kh  = h >> 2;          // GQA: 4 q-heads per kv-head
    const float* Kbase = Kc + (size_t)kh * S_LEN * HD;
    const float* Vbase = Vc + (size_t)kh * S_LEN * HD;

    // Load Q tile transposed: Qs[d][m]
    #pragma unroll
    for (int it = 0; it < 16; it++) {
        int slot = tid + it * 256;            // 0..4095 float4 slots
        int m  = slot >> 5;
        int d4 = (slot & 31) << 2;
        float4 q = *(const float4*)(Q + (size_t)(r0 + m) * HID + h * HD + d4);
        Qs[(d4 + 0) * 128 + m] = q.x;
        Qs[(d4 + 1) * 128 + m] = q.y;
        Qs[(d4 + 2) * 128 + m] = q.z;
        Qs[(d4 + 3) * 128 + m] = q.w;
    }
    if (tid < 128) { m_s[tid] = -CUDART_INF_F; l_s[tid] = 0.0f; }

    const int sx = tid & 7,  sy = tid >> 3;   // S phase: n0=sx*8, m=sy*4..+3
    const int tx = tid & 15, ty = tid >> 4;   // O phase: d0=tx*8, m=ty*8..+7
    const int n0  = sx << 3;
    const int m0s = sy << 2;
    const int m0o = ty << 3;
    const int d0  = tx << 3;

    unsigned long long acc_o[8][4];
    #pragma unroll
    for (int i = 0; i < 8; i++)
        #pragma unroll
        for (int j = 0; j < 4; j++) acc_o[i][j] = 0ull;

    const float SCALE = 0.08838834764831845f;  // 1/sqrt(128)

    for (int j0 = 0; j0 <= r0 + 127; j0 += 64) {
        // Load K (transposed) and V tiles
        #pragma unroll
        for (int it = 0; it < 8; it++) {
            int slot = tid + it * 256;          // 0..2047 float4 slots
            int n  = slot >> 5;
            int d4 = (slot & 31) << 2;
            float4 kv = *(const float4*)(Kbase + (size_t)(j0 + n) * HD + d4);
            Ks[(d4 + 0) * 64 + n] = kv.x;
            Ks[(d4 + 1) * 64 + n] = kv.y;
            Ks[(d4 + 2) * 64 + n] = kv.z;
            Ks[(d4 + 3) * 64 + n] = kv.w;
            float4 vv = *(const float4*)(Vbase + (size_t)(j0 + n) * HD + d4);
            *(float4*)&Vs[n * 128 + d4] = vv;
        }
        __syncthreads();

        // S = Q K^T (4m x 8n microtile per thread)
        unsigned long long acc_s[4][4];
        #pragma unroll
        for (int i = 0; i < 4; i++)
            #pragma unroll
            for (int j = 0; j < 4; j++) acc_s[i][j] = 0ull;

        #pragma unroll 8
        for (int d = 0; d < 128; d++) {
            float4 a = *(const float4*)&Qs[d * 128 + m0s];
            const unsigned long long* kp =
                (const unsigned long long*)&Ks[d * 64 + n0];
            unsigned long long b0 = kp[0], b1 = kp[1], b2 = kp[2], b3 = kp[3];
            float am[4] = {a.x, a.y, a.z, a.w};
            #pragma unroll
            for (int i = 0; i < 4; i++) {
                unsigned long long ad = pack_dup(am[i]);
                fma2(acc_s[i][0], ad, b0);
                fma2(acc_s[i][1], ad, b1);
                fma2(acc_s[i][2], ad, b2);
                fma2(acc_s[i][3], ad, b3);
            }
        }

        // Scale + causal mask + store transposed into Ps[n][m]
        #pragma unroll
        for (int i = 0; i < 4; i++) {
            int m  = m0s + i;
            int sg = r0 + m;
            #pragma unroll
            for (int j = 0; j < 4; j++) {
                int n  = n0 + (j << 1);
                float lo = lo32(acc_s[i][j]) * SCALE;
                float hi = hi32(acc_s[i][j]) * SCALE;
                if (j0 + n     > sg) lo = -10000.0f;
                if (j0 + n + 1 > sg) hi = -10000.0f;
                Ps[(n)     * 128 + m] = lo;
                Ps[(n + 1) * 128 + m] = hi;
            }
        }
        __syncthreads();

        // Online softmax (one row per thread, 128 active threads)
        if (tid < 128) {
            int m = tid;
            float mo = m_s[m];
            float mx = -CUDART_INF_F;
            #pragma unroll 8
            for (int n = 0; n < 64; n++) mx = fmaxf(mx, Ps[n * 128 + m]);
            float mn = fmaxf(mo, mx);
            float alpha = __expf(mo - mn);
            float sum = 0.0f;
            #pragma unroll 8
            for (int n = 0; n < 64; n++) {
                float p = __expf(Ps[n * 128 + m] - mn);
                Ps[n * 128 + m] = p;
                sum += p;
            }
            l_s[m] = l_s[m] * alpha + sum;
            m_s[m] = mn;
            a_s[m] = alpha;
        }
        __syncthreads();

        // Rescale O, then O += P @ V (8m x 8d microtile)
        #pragma unroll
        for (int i = 0; i < 8; i++) {
            unsigned long long av = pack_dup(a_s[m0o + i]);
            #pragma unroll
            for (int j = 0; j < 4; j++) mul2(acc_o[i][j], av);
        }
        #pragma unroll 4
        for (int n = 0; n < 64; n++) {
            float4 p0 = *(const float4*)&Ps[n * 128 + m0o];
            float4 p1 = *(const float4*)&Ps[n * 128 + m0o + 4];
            const unsigned long long* vp =
                (const unsigned long long*)&Vs[n * 128 + d0];
            unsigned long long v0 = vp[0], v1 = vp[1], v2 = vp[2], v3 = vp[3];
            float pm[8] = {p0.x, p0.y, p0.z, p0.w, p1.x, p1.y, p1.z, p1.w};
            #pragma unroll
            for (int i = 0; i < 8; i++) {
                unsigned long long pd = pack_dup(pm[i]);
                fma2(acc_o[i][0], pd, v0);
                fma2(acc_o[i][1], pd, v1);
                fma2(acc_o[i][2], pd, v2);
                fma2(acc_o[i][3], pd, v3);
            }
        }
        __syncthreads();
    }

    // Normalize and write out: O[s][h*128+d]
    #pragma unroll
    for (int i = 0; i < 8; i++) {
        float inv = 1.0f / l_s[m0o + i];
        float4 v0 = make_float4(lo32(acc_o[i][0]) * inv, hi32(acc_o[i][0]) * inv,
                                lo32(acc_o[i][1]) * inv, hi32(acc_o[i][1]) * inv);
        float4 v1 = make_float4(lo32(acc_o[i][2]) * inv, hi32(acc_o[i][2]) * inv,
                                lo32(acc_o[i][3]) * inv, hi32(acc_o[i][3]) * inv);
        float* op = O + (size_t)(r0 + m0o + i) * HID + h * HD + d0;
        *(float4*)op       = v0;
        *(float4*)(op + 4) = v1;
    }
}

// ---------------- launcher ----------------------------------------------------
extern "C" void kernel_launch(void* const* d_in, const int* in_sizes, int n_in,
                              void* d_out, int out_size) {
    const float* hidden  = (const float*)d_in[0];   // [1,2048,4096]
    const float* k_cache = (const float*)d_in[1];   // [1,8,2048,128]
    const float* v_cache = (const float*)d_in[2];   // [1,8,2048,128]
    const float* Wq      = (const float*)d_in[3];   // [4096,4096]
    const float* Wo      = (const float*)d_in[4];   // [4096,4096]
    const int*   pos     = (const int*)d_in[5];     // [1,2048]
    // d_in[6] = attention_mask (causal triu, implemented analytically)
    float* out = (float*)d_out;                     // [1,2048,4096] f32

    float *qbuf, *obuf;
    cudaGetSymbolAddress((void**)&qbuf, g_Q);
    cudaGetSymbolAddress((void**)&obuf, g_O);

    dim3 gGemm(HID / 128, S_LEN / 128);   // (32, 16)

    // 1) Q projection
    sgemm128<<<gGemm, 256>>>(hidden, Wq, qbuf, S_LEN, HID, HID);

    // 2) RoPE in-place
    rope_kernel<<<(S_LEN * NH * 64) / 256, 256>>>(qbuf, pos);

    // 3) Flash attention
    size_t smem_attn = (size_t)(128 * 128 + 128 * 64 + 64 * 128 + 64 * 128 + 3 * 128)
                       * sizeof(float);  // 165376 B
    cudaFuncSetAttribute(attn_kernel,
                         cudaFuncAttributeMaxDynamicSharedMemorySize,
                         (int)smem_attn);
    dim3 gAttn(S_LEN / 128, NH);          // (16, 32)
    attn_kernel<<<gAttn, 256, smem_attn>>>(qbuf, k_cache, v_cache, obuf);

    // 4) Output projection
    sgemm128<<<gGemm, 256>>>(obuf, Wo, out, S_LEN, HID, HID);
}

// round 9
// speedup vs baseline: 1.6753x; 1.6753x over previous
#include <cuda_runtime.h>
#include <cuda_bf16.h>
#include <math_constants.h>
#include <cstdint>

// Problem constants
#define S_LEN 2048
#define HID   4096
#define KDIM  4096
#define NH    32
#define NKV   8
#define HD    128
#define SPAD  72    // smem row stride in bf16 (144 B -> 4-bank shift per row)

// ---------------- scratch (__device__ globals; no allocation APIs) -----------
__device__ float g_Q[S_LEN * HID];           // Q after proj+rope
__device__ float g_O[S_LEN * HID];           // attention output
__device__ __nv_bfloat16 g_Ah[S_LEN * HID];  // split A (hi)
__device__ __nv_bfloat16 g_Al[S_LEN * HID];  // split A (lo)
__device__ __nv_bfloat16 g_Bh[HID * HID];    // split, transposed W (hi) [n][k]
__device__ __nv_bfloat16 g_Bl[HID * HID];    // split, transposed W (lo) [n][k]

// ---------------- packed f32x2 helpers (attention path) ----------------------
__device__ __forceinline__ unsigned long long pack_dup(float x) {
    unsigned long long r; unsigned int u = __float_as_uint(x);
    asm("mov.b64 %0, {%1, %1};" : "=l"(r) : "r"(u));
    return r;
}
__device__ __forceinline__ void fma2(unsigned long long& d,
                                     unsigned long long a, unsigned long long b) {
    asm("fma.rn.f32x2 %0, %1, %2, %0;" : "+l"(d) : "l"(a), "l"(b));
}
__device__ __forceinline__ void mul2(unsigned long long& d, unsigned long long a) {
    asm("mul.rn.f32x2 %0, %1, %0;" : "+l"(d) : "l"(a));
}
__device__ __forceinline__ float lo32(unsigned long long v) {
    return __uint_as_float((unsigned int)(v & 0xffffffffull));
}
__device__ __forceinline__ float hi32(unsigned long long v) {
    return __uint_as_float((unsigned int)(v >> 32));
}

// ---------------- mma.sync helper (portable sm_80+ PTX) -----------------------
__device__ __forceinline__ void mma16816(float* d, const uint32_t* a,
                                         const uint32_t* b) {
    asm volatile(
        "mma.sync.aligned.m16n8k16.row.col.f32.bf16.bf16.f32 "
        "{%0,%1,%2,%3}, {%4,%5,%6,%7}, {%8,%9}, {%0,%1,%2,%3};"
        : "+f"(d[0]), "+f"(d[1]), "+f"(d[2]), "+f"(d[3])
        : "r"(a[0]), "r"(a[1]), "r"(a[2]), "r"(a[3]), "r"(b[0]), "r"(b[1]));
}
__device__ __forceinline__ void cp_async16(uint32_t dst, const void* src) {
    asm volatile("cp.async.ca.shared.global [%0], [%1], 16;"
                 :: "r"(dst), "l"(src));
}
__device__ __forceinline__ uint32_t smem_u32(const void* p) {
    uint32_t a;
    asm("{ .reg .u64 t; cvta.to.shared.u64 t, %1; cvt.u32.u64 %0, t; }"
        : "=r"(a) : "l"(p));
    return a;
}

// ---------------- split conversion kernels -----------------------------------
__global__ __launch_bounds__(256)
void conv_split_kernel(const float4* __restrict__ in,
                       uint2* __restrict__ hi, uint2* __restrict__ lo) {
    int i = blockIdx.x * blockDim.x + threadIdx.x;
    float4 v = in[i];
    __nv_bfloat16 h0 = __float2bfloat16(v.x), h1 = __float2bfloat16(v.y);
    __nv_bfloat16 h2 = __float2bfloat16(v.z), h3 = __float2bfloat16(v.w);
    __nv_bfloat16 l0 = __float2bfloat16(v.x - __bfloat162float(h0));
    __nv_bfloat16 l1 = __float2bfloat16(v.y - __bfloat162float(h1));
    __nv_bfloat16 l2 = __float2bfloat16(v.z - __bfloat162float(h2));
    __nv_bfloat16 l3 = __float2bfloat16(v.w - __bfloat162float(h3));
    uint2 H, L;
    H.x = (uint32_t)__bfloat16_as_ushort(h0) | ((uint32_t)__bfloat16_as_ushort(h1) << 16);
    H.y = (uint32_t)__bfloat16_as_ushort(h2) | ((uint32_t)__bfloat16_as_ushort(h3) << 16);
    L.x = (uint32_t)__bfloat16_as_ushort(l0) | ((uint32_t)__bfloat16_as_ushort(l1) << 16);
    L.y = (uint32_t)__bfloat16_as_ushort(l2) | ((uint32_t)__bfloat16_as_ushort(l3) << 16);
    hi[i] = H; lo[i] = L;
}

__global__ __launch_bounds__(256)
void conv_split_T_kernel(const float* __restrict__ W,
                         __nv_bfloat16* __restrict__ Th,
                         __nv_bfloat16* __restrict__ Tl) {
    __shared__ float tile[32][33];
    int tx = threadIdx.x, ty = threadIdx.y;       // (32, 8)
    int n0 = blockIdx.x * 32, k0 = blockIdx.y * 32;
    #pragma unroll
    for (int i = 0; i < 4; i++)
        tile[ty + i * 8][tx] = W[(size_t)(k0 + ty + i * 8) * HID + n0 + tx];
    __syncthreads();
    #pragma unroll
    for (int i = 0; i < 4; i++) {
        float v = tile[tx][ty + i * 8];
        __nv_bfloat16 h = __float2bfloat16(v);
        __nv_bfloat16 l = __float2bfloat16(v - __bfloat162float(h));
        size_t o = (size_t)(n0 + ty + i * 8) * KDIM + k0 + tx;
        Th[o] = h; Tl[o] = l;
    }
}

// ---------------- mma.sync GEMM: C = A @ W, split-bf16 3-term ----------------
// CTA tile 128x128, 8 warps (2m x 4n -> 64x32 warp tile), K-chunks of 64,
// double-buffered smem filled by cp.async. D = Ah*Bh + Ah*Bl + Al*Bh.
__global__ __launch_bounds__(256)
void gemm_mma(const __nv_bfloat16* __restrict__ Ah, const __nv_bfloat16* __restrict__ Al,
              const __nv_bfloat16* __restrict__ Bh, const __nv_bfloat16* __restrict__ Bl,
              float* __restrict__ C) {
    extern __shared__ __align__(16) __nv_bfloat16 sm[];  // [2][4][128][SPAD]
    const uint32_t sb = smem_u32(sm);
    const int tid = threadIdx.x;
    const int wid = tid >> 5, lane = tid & 31;
    const int wm = wid >> 2, wn = wid & 3;   // 2 x 4 warp grid
    const int gid = lane >> 2, t4 = lane & 3;
    const int m0 = blockIdx.y * 128, n0 = blockIdx.x * 128;

    const __nv_bfloat16* b0p = Ah + (size_t)m0 * KDIM;
    const __nv_bfloat16* b1p = Al + (size_t)m0 * KDIM;
    const __nv_bfloat16* b2p = Bh + (size_t)n0 * KDIM;
    const __nv_bfloat16* b3p = Bl + (size_t)n0 * KDIM;

    const uint32_t TILE = 128u * SPAD * 2u;       // bytes per tile
    const uint32_t STAGE = 4u * TILE;             // bytes per stage

    float acc[4][4][4];
    #pragma unroll
    for (int i = 0; i < 4; i++)
        #pragma unroll
        for (int j = 0; j < 4; j++)
            #pragma unroll
            for (int q = 0; q < 4; q++) acc[i][j][q] = 0.0f;

    auto load_stage = [&](int c, int s) {
        const uint32_t sbase = sb + (uint32_t)s * STAGE;
        #pragma unroll
        for (int t = 0; t < 16; t++) {
            int id = tid + t * 256;              // 0..4095
            int tile = id >> 10;
            int rem = id & 1023;
            int row = rem >> 3, j = rem & 7;
            const __nv_bfloat16* src =
                ((tile == 0) ? b0p : (tile == 1) ? b1p : (tile == 2) ? b2p : b3p)
                + (size_t)row * KDIM + c * 64 + j * 8;
            uint32_t dst = sbase + (uint32_t)tile * TILE
                         + ((uint32_t)row * SPAD + (uint32_t)j * 8) * 2u;
            cp_async16(dst, src);
        }
        asm volatile("cp.async.commit_group;" ::: "memory");
    };

    const int NC = KDIM / 64;   // 64 chunks
    load_stage(0, 0);

    for (int c = 0; c < NC; c++) {
        if (c + 1 < NC) {
            load_stage(c + 1, (c + 1) & 1);
            asm volatile("cp.async.wait_group 1;" ::: "memory");
        } else {
            asm volatile("cp.async.wait_group 0;" ::: "memory");
        }
        __syncthreads();

        const __nv_bfloat16* sAh = sm + (size_t)(c & 1) * 4 * 128 * SPAD;
        const __nv_bfloat16* sAl = sAh + 128 * SPAD;
        const __nv_bfloat16* sBh = sAl + 128 * SPAD;
        const __nv_bfloat16* sBl = sBh + 128 * SPAD;

        #pragma unroll
        for (int ks = 0; ks < 4; ks++) {
            const int k = ks * 16 + t4 * 2;
            uint32_t ah[4][4], al[4][4];
            #pragma unroll
            for (int mf = 0; mf < 4; mf++) {
                int m = wm * 64 + mf * 16 + gid;
                ah[mf][0] = *(const uint32_t*)&sAh[m * SPAD + k];
                ah[mf][1] = *(const uint32_t*)&sAh[(m + 8) * SPAD + k];
                ah[mf][2] = *(const uint32_t*)&sAh[m * SPAD + k + 8];
                ah[mf][3] = *(const uint32_t*)&sAh[(m + 8) * SPAD + k + 8];
                al[mf][0] = *(const uint32_t*)&sAl[m * SPAD + k];
                al[mf][1] = *(const uint32_t*)&sAl[(m + 8) * SPAD + k];
                al[mf][2] = *(const uint32_t*)&sAl[m * SPAD + k + 8];
                al[mf][3] = *(const uint32_t*)&sAl[(m + 8) * SPAD + k + 8];
            }
            uint32_t bh[4][2], bl[4][2];
            #pragma unroll
            for (int nf = 0; nf < 4; nf++) {
                int n = wn * 32 + nf * 8 + gid;
                bh[nf][0] = *(const uint32_t*)&sBh[n * SPAD + k];
                bh[nf][1] = *(const uint32_t*)&sBh[n * SPAD + k + 8];
                bl[nf][0] = *(const uint32_t*)&sBl[n * SPAD + k];
                bl[nf][1] = *(const uint32_t*)&sBl[n * SPAD + k + 8];
            }
            #pragma unroll
            for (int mf = 0; mf < 4; mf++)
                #pragma unroll
                for (int nf = 0; nf < 4; nf++) {
                    mma16816(acc[mf][nf], ah[mf], bh[nf]);
                    mma16816(acc[mf][nf], ah[mf], bl[nf]);
                    mma16816(acc[mf][nf], al[mf], bh[nf]);
                }
        }
        __syncthreads();
    }

    // Epilogue: m16n8 frag -> C. c0,c1 at (row, col..col+1); c2,c3 at row+8.
    #pragma unroll
    for (int mf = 0; mf < 4; mf++)
        #pragma unroll
        for (int nf = 0; nf < 4; nf++) {
            int row = m0 + wm * 64 + mf * 16 + gid;
            int col = n0 + wn * 32 + nf * 8 + t4 * 2;
            float2 v0 = make_float2(acc[mf][nf][0], acc[mf][nf][1]);
            float2 v1 = make_float2(acc[mf][nf][2], acc[mf][nf][3]);
            *(float2*)&C[(size_t)row * HID + col]       = v0;
            *(float2*)&C[(size_t)(row + 8) * HID + col] = v1;
        }
}

// ---------------- RoPE (in-place on g_Q) -------------------------------------
__global__ void rope_kernel(float* __restrict__ Q, const int* __restrict__ pos) {
    int t = blockIdx.x * blockDim.x + threadIdx.x;
    int i = t & 63;
    int h = (t >> 6) & 31;
    int s = t >> 11;
    float inv = expf(-(float)i * 0.14391156384599196f);  // ln(10000)/64
    float ang = (float)pos[s] * inv;
    float sn, cs;
    sincosf(ang, &sn, &cs);
    float* p = Q + (size_t)s * HID + h * HD + i;
    float x1 = p[0], x2 = p[64];
    p[0]  = x1 * cs - x2 * sn;
    p[64] = x2 * cs + x1 * sn;
}

// ---------------- Flash attention (causal, GQA) -------------------------------
__global__ __launch_bounds__(256)
void attn_kernel(const float* __restrict__ Q, const float* __restrict__ Kc,
                 const float* __restrict__ Vc, float* __restrict__ O) {
    extern __shared__ float smf[];
    float* Qs  = smf;                // [d][m]   128x128 (transposed)
    float* Ks  = Qs + 128 * 128;     // [d][n]   128x64  (transposed)
    float* Vs  = Ks + 128 * 64;      // [n][d]   64x128
    float* Ps  = Vs + 64 * 128;      // [n][m]   64x128  (transposed S/P tile)
    float* m_s = Ps + 64 * 128;      // [128]
    float* l_s = m_s + 128;          // [128]
    float* a_s = l_s + 128;          // [128]

    const int tid = threadIdx.x;
    const int qt  = (int)gridDim.x - 1 - (int)blockIdx.x;  // heavy tiles first
    const int h   = blockIdx.y;
    const int r0  = qt * 128;
    const int kh  = h >> 2;
    const float* Kbase = Kc + (size_t)kh * S_LEN * HD;
    const float* Vbase = Vc + (size_t)kh * S_LEN * HD;

    #pragma unroll
    for (int it = 0; it < 16; it++) {
        int slot = tid + it * 256;
        int m  = slot >> 5;
        int d4 = (slot & 31) << 2;
        float4 q = *(const float4*)(Q + (size_t)(r0 + m) * HID + h * HD + d4);
        Qs[(d4 + 0) * 128 + m] = q.x;
        Qs[(d4 + 1) * 128 + m] = q.y;
        Qs[(d4 + 2) * 128 + m] = q.z;
        Qs[(d4 + 3) * 128 + m] = q.w;
    }
    if (tid < 128) { m_s[tid] = -CUDART_INF_F; l_s[tid] = 0.0f; }

    const int sx = tid & 7,  sy = tid >> 3;
    const int tx = tid & 15, ty = tid >> 4;
    const int n0  = sx << 3;
    const int m0s = sy << 2;
    const int m0o = ty << 3;
    const int d0  = tx << 3;

    unsigned long long acc_o[8][4];
    #pragma unroll
    for (int i = 0; i < 8; i++)
        #pragma unroll
        for (int j = 0; j < 4; j++) acc_o[i][j] = 0ull;

    const float SCALE = 0.08838834764831845f;

    for (int j0 = 0; j0 <= r0 + 127; j0 += 64) {
        #pragma unroll
        for (int it = 0; it < 8; it++) {
            int slot = tid + it * 256;
            int n  = slot >> 5;
            int d4 = (slot & 31) << 2;
            float4 kv = *(const float4*)(Kbase + (size_t)(j0 + n) * HD + d4);
            Ks[(d4 + 0) * 64 + n] = kv.x;
            Ks[(d4 + 1) * 64 + n] = kv.y;
            Ks[(d4 + 2) * 64 + n] = kv.z;
            Ks[(d4 + 3) * 64 + n] = kv.w;
            float4 vv = *(const float4*)(Vbase + (size_t)(j0 + n) * HD + d4);
            *(float4*)&Vs[n * 128 + d4] = vv;
        }
        __syncthreads();

        unsigned long long acc_s[4][4];
        #pragma unroll
        for (int i = 0; i < 4; i++)
            #pragma unroll
            for (int j = 0; j < 4; j++) acc_s[i][j] = 0ull;

        #pragma unroll 8
        for (int d = 0; d < 128; d++) {
            float4 a = *(const float4*)&Qs[d * 128 + m0s];
            const unsigned long long* kp =
                (const unsigned long long*)&Ks[d * 64 + n0];
            unsigned long long b0 = kp[0], b1 = kp[1], b2 = kp[2], b3 = kp[3];
            float am[4] = {a.x, a.y, a.z, a.w};
            #pragma unroll
            for (int i = 0; i < 4; i++) {
                unsigned long long ad = pack_dup(am[i]);
                fma2(acc_s[i][0], ad, b0);
                fma2(acc_s[i][1], ad, b1);
                fma2(acc_s[i][2], ad, b2);
                fma2(acc_s[i][3], ad, b3);
            }
        }

        #pragma unroll
        for (int i = 0; i < 4; i++) {
            int m  = m0s + i;
            int sg = r0 + m;
            #pragma unroll
            for (int j = 0; j < 4; j++) {
                int n  = n0 + (j << 1);
                float lo = lo32(acc_s[i][j]) * SCALE;
                float hi = hi32(acc_s[i][j]) * SCALE;
                if (j0 + n     > sg) lo = -10000.0f;
                if (j0 + n + 1 > sg) hi = -10000.0f;
                Ps[(n)     * 128 + m] = lo;
                Ps[(n + 1) * 128 + m] = hi;
            }
        }
        __syncthreads();

        if (tid < 128) {
            int m = tid;
            float mo = m_s[m];
            float mx = -CUDART_INF_F;
            #pragma unroll 8
            for (int n = 0; n < 64; n++) mx = fmaxf(mx, Ps[n * 128 + m]);
            float mn = fmaxf(mo, mx);
            float alpha = __expf(mo - mn);
            float sum = 0.0f;
            #pragma unroll 8
            for (int n = 0; n < 64; n++) {
                float p = __expf(Ps[n * 128 + m] - mn);
                Ps[n * 128 + m] = p;
                sum += p;
            }
            l_s[m] = l_s[m] * alpha + sum;
            m_s[m] = mn;
            a_s[m] = alpha;
        }
        __syncthreads();

        #pragma unroll
        for (int i = 0; i < 8; i++) {
            unsigned long long av = pack_dup(a_s[m0o + i]);
            #pragma unroll
            for (int j = 0; j < 4; j++) mul2(acc_o[i][j], av);
        }
        #pragma unroll 4
        for (int n = 0; n < 64; n++) {
            float4 p0 = *(const float4*)&Ps[n * 128 + m0o];
            float4 p1 = *(const float4*)&Ps[n * 128 + m0o + 4];
            const unsigned long long* vp =
                (const unsigned long long*)&Vs[n * 128 + d0];
            unsigned long long v0 = vp[0], v1 = vp[1], v2 = vp[2], v3 = vp[3];
            float pm[8] = {p0.x, p0.y, p0.z, p0.w, p1.x, p1.y, p1.z, p1.w};
            #pragma unroll
            for (int i = 0; i < 8; i++) {
                unsigned long long pd = pack_dup(pm[i]);
                fma2(acc_o[i][0], pd, v0);
                fma2(acc_o[i][1], pd, v1);
                fma2(acc_o[i][2], pd, v2);
                fma2(acc_o[i][3], pd, v3);
            }
        }
        __syncthreads();
    }

    #pragma unroll
    for (int i = 0; i < 8; i++) {
        float inv = 1.0f / l_s[m0o + i];
        float4 v0 = make_float4(lo32(acc_o[i][0]) * inv, hi32(acc_o[i][0]) * inv,
                                lo32(acc_o[i][1]) * inv, hi32(acc_o[i][1]) * inv);
        float4 v1 = make_float4(lo32(acc_o[i][2]) * inv, hi32(acc_o[i][2]) * inv,
                                lo32(acc_o[i][3]) * inv, hi32(acc_o[i][3]) * inv);
        float* op = O + (size_t)(r0 + m0o + i) * HID + h * HD + d0;
        *(float4*)op       = v0;
        *(float4*)(op + 4) = v1;
    }
}

// ---------------- launcher ----------------------------------------------------
extern "C" void kernel_launch(void* const* d_in, const int* in_sizes, int n_in,
                              void* d_out, int out_size) {
    const float* hidden  = (const float*)d_in[0];
    const float* k_cache = (const float*)d_in[1];
    const float* v_cache = (const float*)d_in[2];
    const float* Wq      = (const float*)d_in[3];
    const float* Wo      = (const float*)d_in[4];
    const int*   pos     = (const int*)d_in[5];
    float* out = (float*)d_out;

    float *qbuf, *obuf;
    __nv_bfloat16 *ah, *al, *bh, *bl;
    cudaGetSymbolAddress((void**)&qbuf, g_Q);
    cudaGetSymbolAddress((void**)&obuf, g_O);
    cudaGetSymbolAddress((void**)&ah, g_Ah);
    cudaGetSymbolAddress((void**)&al, g_Al);
    cudaGetSymbolAddress((void**)&bh, g_Bh);
    cudaGetSymbolAddress((void**)&bl, g_Bl);

    const int gemm_smem = 2 * 4 * 128 * SPAD * 2;   // 147456 B
    cudaFuncSetAttribute(gemm_mma, cudaFuncAttributeMaxDynamicSharedMemorySize,
                         gemm_smem);
    size_t smem_attn = (size_t)(128 * 128 + 128 * 64 + 64 * 128 + 64 * 128 + 3 * 128)
                       * sizeof(float);             // 165376 B
    cudaFuncSetAttribute(attn_kernel, cudaFuncAttributeMaxDynamicSharedMemorySize,
                         (int)smem_attn);

    dim3 gGemm(HID / 128, S_LEN / 128);             // (32, 16)
    dim3 gT(HID / 32, HID / 32);                    // (128, 128)
    dim3 bT(32, 8);
    int convBlocks = (S_LEN * HID / 4) / 256;       // 8192

    // 1) Q projection: split-convert, then mma.sync GEMM
    conv_split_kernel<<<convBlocks, 256>>>((const float4*)hidden, (uint2*)ah, (uint2*)al);
    conv_split_T_kernel<<<gT, bT>>>(Wq, bh, bl);
    gemm_mma<<<gGemm, 256, gemm_smem>>>(ah, al, bh, bl, qbuf);

    // 2) RoPE in-place
    rope_kernel<<<(S_LEN * NH * 64) / 256, 256>>>(qbuf, pos);

    // 3) Flash attention
    dim3 gAttn(S_LEN / 128, NH);
    attn_kernel<<<gAttn, 256, smem_attn>>>(qbuf, k_cache, v_cache, obuf);

    // 4) Output projection
    conv_split_kernel<<<convBlocks, 256>>>((const float4*)obuf, (uint2*)ah, (uint2*)al);
    conv_split_T_kernel<<<gT, bT>>>(Wo, bh, bl);
    gemm_mma<<<gGemm, 256, gemm_smem>>>(ah, al, bh, bl, out);
}

// round 10
// speedup vs baseline: 2.4002x; 1.4327x over previous
#include <cuda_runtime.h>
#include <cuda_bf16.h>
#include <math_constants.h>
#include <cstdint>

// Problem constants
#define S_LEN 2048
#define HID   4096
#define KDIM  4096
#define NH    32
#define NKV   8
#define HD    128
#define SPAD  72    // gemm smem row stride in bf16

// ---------------- scratch (__device__ globals; no allocation APIs) -----------
__device__ float g_Q[S_LEN * HID];           // Q after proj+rope
__device__ float g_O[S_LEN * HID];           // attention output
__device__ __nv_bfloat16 g_Ah[S_LEN * HID];  // split A (hi)
__device__ __nv_bfloat16 g_Al[S_LEN * HID];  // split A (lo)
__device__ __nv_bfloat16 g_Bh[HID * HID];    // split, transposed W (hi) [n][k]
__device__ __nv_bfloat16 g_Bl[HID * HID];    // split, transposed W (lo) [n][k]

// ---------------- mma.sync helpers (portable sm_80+ PTX) ----------------------
__device__ __forceinline__ void mma16816(float* d, const uint32_t* a,
                                         const uint32_t* b) {
    asm volatile(
        "mma.sync.aligned.m16n8k16.row.col.f32.bf16.bf16.f32 "
        "{%0,%1,%2,%3}, {%4,%5,%6,%7}, {%8,%9}, {%0,%1,%2,%3};"
        : "+f"(d[0]), "+f"(d[1]), "+f"(d[2]), "+f"(d[3])
        : "r"(a[0]), "r"(a[1]), "r"(a[2]), "r"(a[3]), "r"(b[0]), "r"(b[1]));
}
__device__ __forceinline__ void cp_async16(uint32_t dst, const void* src) {
    asm volatile("cp.async.ca.shared.global [%0], [%1], 16;"
                 :: "r"(dst), "l"(src));
}
__device__ __forceinline__ uint32_t smem_u32(const void* p) {
    uint32_t a;
    asm("{ .reg .u64 t; cvta.to.shared.u64 t, %1; cvt.u32.u64 %0, t; }"
        : "=r"(a) : "l"(p));
    return a;
}
// split two floats into packed bf16 (hi) and packed bf16 residual (lo)
__device__ __forceinline__ void split2(float x, float y, uint32_t& h, uint32_t& l) {
    __nv_bfloat16 hx = __float2bfloat16(x), hy = __float2bfloat16(y);
    __nv_bfloat16 lx = __float2bfloat16(x - __bfloat162float(hx));
    __nv_bfloat16 ly = __float2bfloat16(y - __bfloat162float(hy));
    h = (uint32_t)__bfloat16_as_ushort(hx) | ((uint32_t)__bfloat16_as_ushort(hy) << 16);
    l = (uint32_t)__bfloat16_as_ushort(lx) | ((uint32_t)__bfloat16_as_ushort(ly) << 16);
}

// ---------------- split conversion kernels -----------------------------------
__global__ __launch_bounds__(256)
void conv_split_kernel(const float4* __restrict__ in,
                       uint2* __restrict__ hi, uint2* __restrict__ lo) {
    int i = blockIdx.x * blockDim.x + threadIdx.x;
    float4 v = in[i];
    uint32_t h01, l01, h23, l23;
    split2(v.x, v.y, h01, l01);
    split2(v.z, v.w, h23, l23);
    hi[i] = make_uint2(h01, h23);
    lo[i] = make_uint2(l01, l23);
}

__global__ __launch_bounds__(256)
void conv_split_T_kernel(const float* __restrict__ W,
                         __nv_bfloat16* __restrict__ Th,
                         __nv_bfloat16* __restrict__ Tl) {
    __shared__ float tile[32][33];
    int tx = threadIdx.x, ty = threadIdx.y;       // (32, 8)
    int n0 = blockIdx.x * 32, k0 = blockIdx.y * 32;
    #pragma unroll
    for (int i = 0; i < 4; i++)
        tile[ty + i * 8][tx] = W[(size_t)(k0 + ty + i * 8) * HID + n0 + tx];
    __syncthreads();
    #pragma unroll
    for (int i = 0; i < 4; i++) {
        float v = tile[tx][ty + i * 8];
        __nv_bfloat16 h = __float2bfloat16(v);
        __nv_bfloat16 l = __float2bfloat16(v - __bfloat162float(h));
        size_t o = (size_t)(n0 + ty + i * 8) * KDIM + k0 + tx;
        Th[o] = h; Tl[o] = l;
    }
}

// ---------------- mma.sync GEMM: C = A @ W, split-bf16 3-term ----------------
__global__ __launch_bounds__(256)
void gemm_mma(const __nv_bfloat16* __restrict__ Ah, const __nv_bfloat16* __restrict__ Al,
              const __nv_bfloat16* __restrict__ Bh, const __nv_bfloat16* __restrict__ Bl,
              float* __restrict__ C) {
    extern __shared__ __align__(16) __nv_bfloat16 sm[];  // [2][4][128][SPAD]
    const uint32_t sb = smem_u32(sm);
    const int tid = threadIdx.x;
    const int wid = tid >> 5, lane = tid & 31;
    const int wm = wid >> 2, wn = wid & 3;   // 2 x 4 warp grid
    const int gid = lane >> 2, t4 = lane & 3;
    const int m0 = blockIdx.y * 128, n0 = blockIdx.x * 128;

    const __nv_bfloat16* b0p = Ah + (size_t)m0 * KDIM;
    const __nv_bfloat16* b1p = Al + (size_t)m0 * KDIM;
    const __nv_bfloat16* b2p = Bh + (size_t)n0 * KDIM;
    const __nv_bfloat16* b3p = Bl + (size_t)n0 * KDIM;

    const uint32_t TILE = 128u * SPAD * 2u;
    const uint32_t STAGE = 4u * TILE;

    float acc[4][4][4];
    #pragma unroll
    for (int i = 0; i < 4; i++)
        #pragma unroll
        for (int j = 0; j < 4; j++)
            #pragma unroll
            for (int q = 0; q < 4; q++) acc[i][j][q] = 0.0f;

    auto load_stage = [&](int c, int s) {
        const uint32_t sbase = sb + (uint32_t)s * STAGE;
        #pragma unroll
        for (int t = 0; t < 16; t++) {
            int id = tid + t * 256;
            int tile = id >> 10;
            int rem = id & 1023;
            int row = rem >> 3, j = rem & 7;
            const __nv_bfloat16* src =
                ((tile == 0) ? b0p : (tile == 1) ? b1p : (tile == 2) ? b2p : b3p)
                + (size_t)row * KDIM + c * 64 + j * 8;
            uint32_t dst = sbase + (uint32_t)tile * TILE
                         + ((uint32_t)row * SPAD + (uint32_t)j * 8) * 2u;
            cp_async16(dst, src);
        }
        asm volatile("cp.async.commit_group;" ::: "memory");
    };

    const int NC = KDIM / 64;
    load_stage(0, 0);

    for (int c = 0; c < NC; c++) {
        if (c + 1 < NC) {
            load_stage(c + 1, (c + 1) & 1);
            asm volatile("cp.async.wait_group 1;" ::: "memory");
        } else {
            asm volatile("cp.async.wait_group 0;" ::: "memory");
        }
        __syncthreads();

        const __nv_bfloat16* sAh = sm + (size_t)(c & 1) * 4 * 128 * SPAD;
        const __nv_bfloat16* sAl = sAh + 128 * SPAD;
        const __nv_bfloat16* sBh = sAl + 128 * SPAD;
        const __nv_bfloat16* sBl = sBh + 128 * SPAD;

        #pragma unroll
        for (int ks = 0; ks < 4; ks++) {
            const int k = ks * 16 + t4 * 2;
            uint32_t ah[4][4], al[4][4];
            #pragma unroll
            for (int mf = 0; mf < 4; mf++) {
                int m = wm * 64 + mf * 16 + gid;
                ah[mf][0] = *(const uint32_t*)&sAh[m * SPAD + k];
                ah[mf][1] = *(const uint32_t*)&sAh[(m + 8) * SPAD + k];
                ah[mf][2] = *(const uint32_t*)&sAh[m * SPAD + k + 8];
                ah[mf][3] = *(const uint32_t*)&sAh[(m + 8) * SPAD + k + 8];
                al[mf][0] = *(const uint32_t*)&sAl[m * SPAD + k];
                al[mf][1] = *(const uint32_t*)&sAl[(m + 8) * SPAD + k];
                al[mf][2] = *(const uint32_t*)&sAl[m * SPAD + k + 8];
                al[mf][3] = *(const uint32_t*)&sAl[(m + 8) * SPAD + k + 8];
            }
            uint32_t bh[4][2], bl[4][2];
            #pragma unroll
            for (int nf = 0; nf < 4; nf++) {
                int n = wn * 32 + nf * 8 + gid;
                bh[nf][0] = *(const uint32_t*)&sBh[n * SPAD + k];
                bh[nf][1] = *(const uint32_t*)&sBh[n * SPAD + k + 8];
                bl[nf][0] = *(const uint32_t*)&sBl[n * SPAD + k];
                bl[nf][1] = *(const uint32_t*)&sBl[n * SPAD + k + 8];
            }
            #pragma unroll
            for (int mf = 0; mf < 4; mf++)
                #pragma unroll
                for (int nf = 0; nf < 4; nf++) {
                    mma16816(acc[mf][nf], ah[mf], bh[nf]);
                    mma16816(acc[mf][nf], ah[mf], bl[nf]);
                    mma16816(acc[mf][nf], al[mf], bh[nf]);
                }
        }
        __syncthreads();
    }

    #pragma unroll
    for (int mf = 0; mf < 4; mf++)
        #pragma unroll
        for (int nf = 0; nf < 4; nf++) {
            int row = m0 + wm * 64 + mf * 16 + gid;
            int col = n0 + wn * 32 + nf * 8 + t4 * 2;
            float2 v0 = make_float2(acc[mf][nf][0], acc[mf][nf][1]);
            float2 v1 = make_float2(acc[mf][nf][2], acc[mf][nf][3]);
            *(float2*)&C[(size_t)row * HID + col]       = v0;
            *(float2*)&C[(size_t)(row + 8) * HID + col] = v1;
        }
}

// ---------------- RoPE (in-place on g_Q) -------------------------------------
__global__ void rope_kernel(float* __restrict__ Q, const int* __restrict__ pos) {
    int t = blockIdx.x * blockDim.x + threadIdx.x;
    int i = t & 63;
    int h = (t >> 6) & 31;
    int s = t >> 11;
    float inv = expf(-(float)i * 0.14391156384599196f);  // ln(10000)/64
    float ang = (float)pos[s] * inv;
    float sn, cs;
    sincosf(ang, &sn, &cs);
    float* p = Q + (size_t)s * HID + h * HD + i;
    float x1 = p[0], x2 = p[64];
    p[0]  = x1 * cs - x2 * sn;
    p[64] = x2 * cs + x1 * sn;
}

// ---------------- Flash attention via mma.sync (causal, GQA) ------------------
// CTA = (128 q rows, head). KV tiles of 64 keys. 8 warps; warp w owns q rows
// 16w..16w+15 and all 64 keys -> softmax is warp-local (quad shuffles).
// QK^T and PV both split-bf16 3-term. P stays in registers (accum frag == A frag).
#define QS 136   // Q/K smem row stride (d-dim, bf16)
#define VS 72    // Vt smem row stride (key-dim, bf16)
__global__ __launch_bounds__(256)
void attn_mma(const float* __restrict__ Q, const float* __restrict__ Kc,
              const float* __restrict__ Vc, float* __restrict__ O) {
    extern __shared__ __align__(16) __nv_bfloat16 sa[];
    __nv_bfloat16* sQh = sa;                 // [128][QS]
    __nv_bfloat16* sQl = sQh + 128 * QS;
    __nv_bfloat16* sKh = sQl + 128 * QS;     // [64][QS]
    __nv_bfloat16* sKl = sKh + 64 * QS;
    __nv_bfloat16* sVh = sKl + 64 * QS;      // [128 d][VS] (transposed V)
    __nv_bfloat16* sVl = sVh + 128 * VS;

    const int tid = threadIdx.x;
    const int wid = tid >> 5, lane = tid & 31;
    const int gid = lane >> 2, t4 = lane & 3;
    const int qt = (int)gridDim.x - 1 - (int)blockIdx.x;  // heavy tiles first
    const int h = blockIdx.y;
    const int r0 = qt * 128;
    const int kh = h >> 2;
    const float* Kbase = Kc + (size_t)kh * S_LEN * HD;
    const float* Vbase = Vc + (size_t)kh * S_LEN * HD;

    // Q tile: load fp32, split to bf16 hi/lo (once per CTA)
    #pragma unroll
    for (int it = 0; it < 16; it++) {
        int slot = tid + it * 256;
        int m = slot >> 5, d4 = (slot & 31) << 2;
        float4 q = *(const float4*)(Q + (size_t)(r0 + m) * HID + h * HD + d4);
        uint32_t h01, l01, h23, l23;
        split2(q.x, q.y, h01, l01);
        split2(q.z, q.w, h23, l23);
        *(uint2*)&sQh[m * QS + d4] = make_uint2(h01, h23);
        *(uint2*)&sQl[m * QS + d4] = make_uint2(l01, l23);
    }

    const int mrow = wid * 16 + gid;
    const float SCALE = 0.08838834764831845f;  // 1/sqrt(128)

    float oacc[16][4];
    #pragma unroll
    for (int nf = 0; nf < 16; nf++)
        #pragma unroll
        for (int q = 0; q < 4; q++) oacc[nf][q] = 0.0f;
    float m0 = -CUDART_INF_F, m1 = -CUDART_INF_F;
    float l0 = 0.0f, l1 = 0.0f;

    const int jend = r0 + 64;
    for (int j0 = 0; j0 <= jend; j0 += 64) {
        __syncthreads();   // previous iteration's smem reads done
        // K tile [64][128] + V tile transposed [128][64], split to bf16
        #pragma unroll
        for (int it = 0; it < 8; it++) {
            int slot = tid + it * 256;
            int n = slot >> 5, d4 = (slot & 31) << 2;
            float4 k4 = *(const float4*)(Kbase + (size_t)(j0 + n) * HD + d4);
            uint32_t h01, l01, h23, l23;
            split2(k4.x, k4.y, h01, l01);
            split2(k4.z, k4.w, h23, l23);
            *(uint2*)&sKh[n * QS + d4] = make_uint2(h01, h23);
            *(uint2*)&sKl[n * QS + d4] = make_uint2(l01, l23);
            float4 v4 = *(const float4*)(Vbase + (size_t)(j0 + n) * HD + d4);
            float vf[4] = {v4.x, v4.y, v4.z, v4.w};
            #pragma unroll
            for (int i = 0; i < 4; i++) {
                __nv_bfloat16 vh = __float2bfloat16(vf[i]);
                __nv_bfloat16 vl = __float2bfloat16(vf[i] - __bfloat162float(vh));
                sVh[(d4 + i) * VS + n] = vh;
                sVl[(d4 + i) * VS + n] = vl;
            }
        }
        __syncthreads();

        // S = Q K^T  (warp: 16 rows x 64 keys, 8 n-frags)
        float sacc[8][4];
        #pragma unroll
        for (int j = 0; j < 8; j++)
            #pragma unroll
            for (int q = 0; q < 4; q++) sacc[j][q] = 0.0f;

        #pragma unroll
        for (int kk = 0; kk < 8; kk++) {
            int k = kk * 16 + t4 * 2;
            uint32_t ah[4], al[4];
            ah[0] = *(const uint32_t*)&sQh[mrow * QS + k];
            ah[1] = *(const uint32_t*)&sQh[(mrow + 8) * QS + k];
            ah[2] = *(const uint32_t*)&sQh[mrow * QS + k + 8];
            ah[3] = *(const uint32_t*)&sQh[(mrow + 8) * QS + k + 8];
            al[0] = *(const uint32_t*)&sQl[mrow * QS + k];
            al[1] = *(const uint32_t*)&sQl[(mrow + 8) * QS + k];
            al[2] = *(const uint32_t*)&sQl[mrow * QS + k + 8];
            al[3] = *(const uint32_t*)&sQl[(mrow + 8) * QS + k + 8];
            #pragma unroll
            for (int j = 0; j < 8; j++) {
                int n = j * 8 + gid;
                uint32_t bh[2] = {*(const uint32_t*)&sKh[n * QS + k],
                                  *(const uint32_t*)&sKh[n * QS + k + 8]};
                uint32_t bl[2] = {*(const uint32_t*)&sKl[n * QS + k],
                                  *(const uint32_t*)&sKl[n * QS + k + 8]};
                mma16816(sacc[j], ah, bh);
                mma16816(sacc[j], ah, bl);
                mma16816(sacc[j], al, bh);
            }
        }

        // scale + causal mask + row max
        const int row0 = r0 + mrow, row1 = row0 + 8;
        float mx0 = -CUDART_INF_F, mx1 = -CUDART_INF_F;
        #pragma unroll
        for (int j = 0; j < 8; j++) {
            int c0 = j0 + j * 8 + t4 * 2, c1 = c0 + 1;
            sacc[j][0] = (c0 > row0) ? -CUDART_INF_F : sacc[j][0] * SCALE;
            sacc[j][1] = (c1 > row0) ? -CUDART_INF_F : sacc[j][1] * SCALE;
            sacc[j][2] = (c0 > row1) ? -CUDART_INF_F : sacc[j][2] * SCALE;
            sacc[j][3] = (c1 > row1) ? -CUDART_INF_F : sacc[j][3] * SCALE;
            mx0 = fmaxf(mx0, fmaxf(sacc[j][0], sacc[j][1]));
            mx1 = fmaxf(mx1, fmaxf(sacc[j][2], sacc[j][3]));
        }
        mx0 = fmaxf(mx0, __shfl_xor_sync(0xffffffffu, mx0, 1));
        mx0 = fmaxf(mx0, __shfl_xor_sync(0xffffffffu, mx0, 2));
        mx1 = fmaxf(mx1, __shfl_xor_sync(0xffffffffu, mx1, 1));
        mx1 = fmaxf(mx1, __shfl_xor_sync(0xffffffffu, mx1, 2));

        float mn0 = fmaxf(m0, mx0), mn1 = fmaxf(m1, mx1);
        float al0 = __expf(m0 - mn0), al1 = __expf(m1 - mn1);
        m0 = mn0; m1 = mn1;

        // exp + pack P to bf16 hi/lo fragments (registers only)
        float s0 = 0.0f, s1 = 0.0f;
        uint32_t ph0[8], ph1[8], pl0[8], pl1[8];
        #pragma unroll
        for (int j = 0; j < 8; j++) {
            float p00 = __expf(sacc[j][0] - mn0);
            float p01 = __expf(sacc[j][1] - mn0);
            float p10 = __expf(sacc[j][2] - mn1);
            float p11 = __expf(sacc[j][3] - mn1);
            s0 += p00 + p01;
            s1 += p10 + p11;
            split2(p00, p01, ph0[j], pl0[j]);
            split2(p10, p11, ph1[j], pl1[j]);
        }
        s0 += __shfl_xor_sync(0xffffffffu, s0, 1);
        s0 += __shfl_xor_sync(0xffffffffu, s0, 2);
        s1 += __shfl_xor_sync(0xffffffffu, s1, 1);
        s1 += __shfl_xor_sync(0xffffffffu, s1, 2);
        l0 = l0 * al0 + s0;
        l1 = l1 * al1 + s1;

        // rescale O accumulators
        #pragma unroll
        for (int nf = 0; nf < 16; nf++) {
            oacc[nf][0] *= al0; oacc[nf][1] *= al0;
            oacc[nf][2] *= al1; oacc[nf][3] *= al1;
        }

        // O += P V  (A frags straight from P registers; B from transposed V)
        #pragma unroll
        for (int kk = 0; kk < 4; kk++) {
            uint32_t ah[4] = {ph0[2 * kk], ph1[2 * kk],
                              ph0[2 * kk + 1], ph1[2 * kk + 1]};
            uint32_t alr[4] = {pl0[2 * kk], pl1[2 * kk],
                               pl0[2 * kk + 1], pl1[2 * kk + 1]};
            int k = kk * 16 + t4 * 2;
            #pragma unroll
            for (int nf = 0; nf < 16; nf++) {
                int n = nf * 8 + gid;
                uint32_t bh[2] = {*(const uint32_t*)&sVh[n * VS + k],
                                  *(const uint32_t*)&sVh[n * VS + k + 8]};
                uint32_t bl[2] = {*(const uint32_t*)&sVl[n * VS + k],
                                  *(const uint32_t*)&sVl[n * VS + k + 8]};
                mma16816(oacc[nf], ah, bh);
                mma16816(oacc[nf], ah, bl);
                mma16816(oacc[nf], alr, bh);
            }
        }
    }

    // normalize + write out
    float inv0 = 1.0f / l0, inv1 = 1.0f / l1;
    #pragma unroll
    for (int nf = 0; nf < 16; nf++) {
        int col = h * HD + nf * 8 + t4 * 2;
        *(float2*)&O[(size_t)(r0 + mrow) * HID + col] =
            make_float2(oacc[nf][0] * inv0, oacc[nf][1] * inv0);
        *(float2*)&O[(size_t)(r0 + mrow + 8) * HID + col] =
            make_float2(oacc[nf][2] * inv1, oacc[nf][3] * inv1);
    }
}

// ---------------- launcher ----------------------------------------------------
extern "C" void kernel_launch(void* const* d_in, const int* in_sizes, int n_in,
                              void* d_out, int out_size) {
    const float* hidden  = (const float*)d_in[0];
    const float* k_cache = (const float*)d_in[1];
    const float* v_cache = (const float*)d_in[2];
    const float* Wq      = (const float*)d_in[3];
    const float* Wo      = (const float*)d_in[4];
    const int*   pos     = (const int*)d_in[5];
    float* out = (float*)d_out;

    float *qbuf, *obuf;
    __nv_bfloat16 *ah, *al, *bh, *bl;
    cudaGetSymbolAddress((void**)&qbuf, g_Q);
    cudaGetSymbolAddress((void**)&obuf, g_O);
    cudaGetSymbolAddress((void**)&ah, g_Ah);
    cudaGetSymbolAddress((void**)&al, g_Al);
    cudaGetSymbolAddress((void**)&bh, g_Bh);
    cudaGetSymbolAddress((void**)&bl, g_Bl);

    const int gemm_smem = 2 * 4 * 128 * SPAD * 2;   // 147456 B
    cudaFuncSetAttribute(gemm_mma, cudaFuncAttributeMaxDynamicSharedMemorySize,
                         gemm_smem);
    const int attn_smem = (2 * 128 * QS + 2 * 64 * QS + 2 * 128 * VS) * 2; // 141312 B
    cudaFuncSetAttribute(attn_mma, cudaFuncAttributeMaxDynamicSharedMemorySize,
                         attn_smem);

    dim3 gGemm(HID / 128, S_LEN / 128);             // (32, 16)
    dim3 gT(HID / 32, HID / 32);                    // (128, 128)
    dim3 bT(32, 8);
    int convBlocks = (S_LEN * HID / 4) / 256;       // 8192

    // 1) Q projection
    conv_split_kernel<<<convBlocks, 256>>>((const float4*)hidden, (uint2*)ah, (uint2*)al);
    conv_split_T_kernel<<<gT, bT>>>(Wq, bh, bl);
    gemm_mma<<<gGemm, 256, gemm_smem>>>(ah, al, bh, bl, qbuf);

    // 2) RoPE in-place
    rope_kernel<<<(S_LEN * NH * 64) / 256, 256>>>(qbuf, pos);

    // 3) Flash attention (tensor-core path)
    dim3 gAttn(S_LEN / 128, NH);
    attn_mma<<<gAttn, 256, attn_smem>>>(qbuf, k_cache, v_cache, obuf);

    // 4) Output projection
    conv_split_kernel<<<convBlocks, 256>>>((const float4*)obuf, (uint2*)ah, (uint2*)al);
    conv_split_T_kernel<<<gT, bT>>>(Wo, bh, bl);
    gemm_mma<<<gGemm, 256, gemm_smem>>>(ah, al, bh, bl, out);
}

// round 13
// speedup vs baseline: 3.0699x; 1.2790x over previous
#include <cuda_runtime.h>
#include <cuda_bf16.h>
#include <math_constants.h>
#include <cstdint>

// Problem constants
#define S_LEN 2048
#define HID   4096
#define KDIM  4096
#define NH    32
#define NKV   8
#define HD    128
#define SPAD  72    // gemm smem row stride in bf16
#define QS    136   // attn Q/K smem row stride (d-dim, bf16)
#define VS    72    // attn Vt smem row stride (key-dim, bf16)

// ---------------- scratch (__device__ globals; no allocation APIs) -----------
__device__ float g_Q[S_LEN * HID];             // Q after proj+rope
__device__ float g_O[S_LEN * HID];             // attention output
__device__ __nv_bfloat16 g_Ah[S_LEN * HID];    // split A (hi)   (also Q hi)
__device__ __nv_bfloat16 g_Al[S_LEN * HID];    // split A (lo)   (also Q lo)
__device__ __nv_bfloat16 g_Bh[HID * HID];      // split, transposed W (hi) [n][k]
__device__ __nv_bfloat16 g_Bl[HID * HID];      // split, transposed W (lo) [n][k]
__device__ __nv_bfloat16 g_Kh[NKV * S_LEN * HD];   // K split hi [kh][s][d]
__device__ __nv_bfloat16 g_Kl[NKV * S_LEN * HD];
__device__ __nv_bfloat16 g_Vth[NKV * HD * S_LEN];  // V split+transposed hi [kh][d][s]
__device__ __nv_bfloat16 g_Vtl[NKV * HD * S_LEN];

// ---------------- mma.sync / ldmatrix helpers (portable sm_80+ PTX) -----------
__device__ __forceinline__ void mma16816(float* d, const uint32_t* a,
                                         const uint32_t* b) {
    asm volatile(
        "mma.sync.aligned.m16n8k16.row.col.f32.bf16.bf16.f32 "
        "{%0,%1,%2,%3}, {%4,%5,%6,%7}, {%8,%9}, {%0,%1,%2,%3};"
        : "+f"(d[0]), "+f"(d[1]), "+f"(d[2]), "+f"(d[3])
        : "r"(a[0]), "r"(a[1]), "r"(a[2]), "r"(a[3]), "r"(b[0]), "r"(b[1]));
}
__device__ __forceinline__ void ldm_x4(uint32_t* r, uint32_t addr) {
    asm volatile("ldmatrix.sync.aligned.m8n8.x4.shared.b16 {%0,%1,%2,%3}, [%4];"
        : "=r"(r[0]), "=r"(r[1]), "=r"(r[2]), "=r"(r[3]) : "r"(addr));
}
__device__ __forceinline__ void cp_async16(uint32_t dst, const void* src) {
    asm volatile("cp.async.ca.shared.global [%0], [%1], 16;"
                 :: "r"(dst), "l"(src));
}
__device__ __forceinline__ uint32_t smem_u32(const void* p) {
    uint32_t a;
    asm("{ .reg .u64 t; cvta.to.shared.u64 t, %1; cvt.u32.u64 %0, t; }"
        : "=r"(a) : "l"(p));
    return a;
}
__device__ __forceinline__ void split2(float x, float y, uint32_t& h, uint32_t& l) {
    __nv_bfloat16 hx = __float2bfloat16(x), hy = __float2bfloat16(y);
    __nv_bfloat16 lx = __float2bfloat16(x - __bfloat162float(hx));
    __nv_bfloat16 ly = __float2bfloat16(y - __bfloat162float(hy));
    h = (uint32_t)__bfloat16_as_ushort(hx) | ((uint32_t)__bfloat16_as_ushort(hy) << 16);
    l = (uint32_t)__bfloat16_as_ushort(lx) | ((uint32_t)__bfloat16_as_ushort(ly) << 16);
}

// ---------------- split conversion kernels -----------------------------------
__global__ __launch_bounds__(256)
void conv_split_kernel(const float4* __restrict__ in,
                       uint2* __restrict__ hi, uint2* __restrict__ lo) {
    int i = blockIdx.x * blockDim.x + threadIdx.x;
    float4 v = in[i];
    uint32_t h01, l01, h23, l23;
    split2(v.x, v.y, h01, l01);
    split2(v.z, v.w, h23, l23);
    hi[i] = make_uint2(h01, h23);
    lo[i] = make_uint2(l01, l23);
}

__global__ __launch_bounds__(256)
void conv_split_T_kernel(const float* __restrict__ W,
                         __nv_bfloat16* __restrict__ Th,
                         __nv_bfloat16* __restrict__ Tl) {
    __shared__ float tile[32][33];
    int tx = threadIdx.x, ty = threadIdx.y;       // (32, 8)
    int n0 = blockIdx.x * 32, k0 = blockIdx.y * 32;
    #pragma unroll
    for (int i = 0; i < 4; i++)
        tile[ty + i * 8][tx] = W[(size_t)(k0 + ty + i * 8) * HID + n0 + tx];
    __syncthreads();
    #pragma unroll
    for (int i = 0; i < 4; i++) {
        float v = tile[tx][ty + i * 8];
        __nv_bfloat16 h = __float2bfloat16(v);
        __nv_bfloat16 l = __float2bfloat16(v - __bfloat162float(h));
        size_t o = (size_t)(n0 + ty + i * 8) * KDIM + k0 + tx;
        Th[o] = h; Tl[o] = l;
    }
}

// V [kh][s][d] -> Vt hi/lo [kh][d][s]
__global__ __launch_bounds__(256)
void conv_split_TV_kernel(const float* __restrict__ V,
                          __nv_bfloat16* __restrict__ Th,
                          __nv_bfloat16* __restrict__ Tl) {
    __shared__ float tile[32][33];
    int kh = blockIdx.z;
    int tx = threadIdx.x, ty = threadIdx.y;       // (32, 8)
    int s0 = blockIdx.x * 32, d0 = blockIdx.y * 32;
    const float* src = V + (size_t)kh * S_LEN * HD;
    #pragma unroll
    for (int i = 0; i < 4; i++)
        tile[ty + i * 8][tx] = src[(size_t)(s0 + ty + i * 8) * HD + d0 + tx];
    __syncthreads();
    #pragma unroll
    for (int i = 0; i < 4; i++) {
        float v = tile[tx][ty + i * 8];   // s_local=tx, d_local=ty+i*8
        __nv_bfloat16 h = __float2bfloat16(v);
        __nv_bfloat16 l = __float2bfloat16(v - __bfloat162float(h));
        size_t o = (size_t)kh * HD * S_LEN + (size_t)(d0 + ty + i * 8) * S_LEN + s0 + tx;
        Th[o] = h; Tl[o] = l;
    }
}

// ---------------- mma.sync GEMM: C = A @ W, split-bf16 3-term ----------------
__global__ __launch_bounds__(256)
void gemm_mma(const __nv_bfloat16* __restrict__ Ah, const __nv_bfloat16* __restrict__ Al,
              const __nv_bfloat16* __restrict__ Bh, const __nv_bfloat16* __restrict__ Bl,
              float* __restrict__ C) {
    extern __shared__ __align__(16) __nv_bfloat16 sm[];  // [2][4][128][SPAD]
    const uint32_t sb = smem_u32(sm);
    const int tid = threadIdx.x;
    const int wid = tid >> 5, lane = tid & 31;
    const int wm = wid >> 2, wn = wid & 3;   // 2 x 4 warp grid
    const int gid = lane >> 2, t4 = lane & 3;
    const int m0 = blockIdx.y * 128, n0 = blockIdx.x * 128;

    // ldmatrix per-lane offsets
    const int a_r = (lane & 7) + ((lane >> 3) & 1) * 8;
    const int a_c = ((lane >> 4) & 1) * 8;
    const int b_r = (lane & 7) + ((lane >> 4) & 1) * 8;
    const int b_c = ((lane >> 3) & 1) * 8;

    const __nv_bfloat16* b0p = Ah + (size_t)m0 * KDIM;
    const __nv_bfloat16* b1p = Al + (size_t)m0 * KDIM;
    const __nv_bfloat16* b2p = Bh + (size_t)n0 * KDIM;
    const __nv_bfloat16* b3p = Bl + (size_t)n0 * KDIM;

    const uint32_t TILE = 128u * SPAD * 2u;
    const uint32_t STAGE = 4u * TILE;

    float acc[4][4][4];
    #pragma unroll
    for (int i = 0; i < 4; i++)
        #pragma unroll
        for (int j = 0; j < 4; j++)
            #pragma unroll
            for (int q = 0; q < 4; q++) acc[i][j][q] = 0.0f;

    auto load_stage = [&](int c, int s) {
        const uint32_t sbase = sb + (uint32_t)s * STAGE;
        #pragma unroll
        for (int t = 0; t < 16; t++) {
            int id = tid + t * 256;
            int tile = id >> 10;
            int rem = id & 1023;
            int row = rem >> 3, j = rem & 7;
            const __nv_bfloat16* src =
                ((tile == 0) ? b0p : (tile == 1) ? b1p : (tile == 2) ? b2p : b3p)
                + (size_t)row * KDIM + c * 64 + j * 8;
            uint32_t dst = sbase + (uint32_t)tile * TILE
                         + ((uint32_t)row * SPAD + (uint32_t)j * 8) * 2u;
            cp_async16(dst, src);
        }
        asm volatile("cp.async.commit_group;" ::: "memory");
    };

    const int NC = KDIM / 64;
    load_stage(0, 0);

    for (int c = 0; c < NC; c++) {
        if (c + 1 < NC) {
            load_stage(c + 1, (c + 1) & 1);
            asm volatile("cp.async.wait_group 1;" ::: "memory");
        } else {
            asm volatile("cp.async.wait_group 0;" ::: "memory");
        }
        __syncthreads();

        const uint32_t sAh = sb + (uint32_t)(c & 1) * STAGE;
        const uint32_t sAl = sAh + TILE;
        const uint32_t sBh = sAl + TILE;
        const uint32_t sBl = sBh + TILE;

        #pragma unroll
        for (int ks = 0; ks < 4; ks++) {
            const int k = ks * 16;
            uint32_t ah[4][4], al[4][4];
            #pragma unroll
            for (int mf = 0; mf < 4; mf++) {
                uint32_t off = (uint32_t)((wm * 64 + mf * 16 + a_r) * SPAD + k + a_c) * 2u;
                ldm_x4(ah[mf], sAh + off);
                ldm_x4(al[mf], sAl + off);
            }
            uint32_t bh[4][2], bl[4][2];
            #pragma unroll
            for (int np = 0; np < 2; np++) {
                uint32_t off = (uint32_t)((wn * 32 + np * 16 + b_r) * SPAD + k + b_c) * 2u;
                ldm_x4(&bh[np * 2][0], sBh + off);
                ldm_x4(&bl[np * 2][0], sBl + off);
            }
            #pragma unroll
            for (int mf = 0; mf < 4; mf++)
                #pragma unroll
                for (int nf = 0; nf < 4; nf++) {
                    mma16816(acc[mf][nf], ah[mf], bh[nf]);
                    mma16816(acc[mf][nf], ah[mf], bl[nf]);
                    mma16816(acc[mf][nf], al[mf], bh[nf]);
                }
        }
        __syncthreads();
    }

    #pragma unroll
    for (int mf = 0; mf < 4; mf++)
        #pragma unroll
        for (int nf = 0; nf < 4; nf++) {
            int row = m0 + wm * 64 + mf * 16 + gid;
            int col = n0 + wn * 32 + nf * 8 + t4 * 2;
            float2 v0 = make_float2(acc[mf][nf][0], acc[mf][nf][1]);
            float2 v1 = make_float2(acc[mf][nf][2], acc[mf][nf][3]);
            *(float2*)&C[(size_t)row * HID + col]       = v0;
            *(float2*)&C[(size_t)(row + 8) * HID + col] = v1;
        }
}

// ---------------- RoPE (in-place on g_Q) -------------------------------------
__global__ void rope_kernel(float* __restrict__ Q, const int* __restrict__ pos) {
    int t = blockIdx.x * blockDim.x + threadIdx.x;
    int i = t & 63;
    int h = (t >> 6) & 31;
    int s = t >> 11;
    float inv = expf(-(float)i * 0.14391156384599196f);  // ln(10000)/64
    float ang = (float)pos[s] * inv;
    float sn, cs;
    sincosf(ang, &sn, &cs);
    float* p = Q + (size_t)s * HID + h * HD + i;
    float x1 = p[0], x2 = p[64];
    p[0]  = x1 * cs - x2 * sn;
    p[64] = x2 * cs + x1 * sn;
}

// ---------------- Flash attention via mma.sync (causal, GQA) ------------------
// Pre-split bf16 inputs; ldmatrix fragment loads; P stays in registers.
__global__ __launch_bounds__(256)
void attn_mma(const __nv_bfloat16* __restrict__ Qh, const __nv_bfloat16* __restrict__ Ql,
              const __nv_bfloat16* __restrict__ Kh, const __nv_bfloat16* __restrict__ Kl,
              const __nv_bfloat16* __restrict__ Vth, const __nv_bfloat16* __restrict__ Vtl,
              float* __restrict__ O) {
    extern __shared__ __align__(16) __nv_bfloat16 sa[];
    __nv_bfloat16* sQh = sa;                 // [128][QS]
    __nv_bfloat16* sQl = sQh + 128 * QS;
    __nv_bfloat16* sKh = sQl + 128 * QS;     // [64][QS]
    __nv_bfloat16* sKl = sKh + 64 * QS;
    __nv_bfloat16* sVh = sKl + 64 * QS;      // [128 d][VS]
    __nv_bfloat16* sVl = sVh + 128 * VS;
    const uint32_t sbase = smem_u32(sa);
    const uint32_t aQh = sbase;
    const uint32_t aQl = aQh + 128u * QS * 2u;
    const uint32_t aKh = aQl + 128u * QS * 2u;
    const uint32_t aKl = aKh + 64u * QS * 2u;
    const uint32_t aVh = aKl + 64u * QS * 2u;
    const uint32_t aVl = aVh + 128u * VS * 2u;

    const int tid = threadIdx.x;
    const int wid = tid >> 5, lane = tid & 31;
    const int gid = lane >> 2, t4 = lane & 3;
    const int a_r = (lane & 7) + ((lane >> 3) & 1) * 8;
    const int a_c = ((lane >> 4) & 1) * 8;
    const int b_r = (lane & 7) + ((lane >> 4) & 1) * 8;
    const int b_c = ((lane >> 3) & 1) * 8;

    const int qt = (int)gridDim.x - 1 - (int)blockIdx.x;  // heavy tiles first
    const int h = blockIdx.y;
    const int r0 = qt * 128;
    const int khd = h >> 2;
    const __nv_bfloat16* Kbh = Kh + (size_t)khd * S_LEN * HD;
    const __nv_bfloat16* Kbl = Kl + (size_t)khd * S_LEN * HD;
    const __nv_bfloat16* Vbh = Vth + (size_t)khd * HD * S_LEN;
    const __nv_bfloat16* Vbl = Vtl + (size_t)khd * HD * S_LEN;

    // Q tile: bf16 hi/lo direct copies (2048 uint4 slots per tensor)
    #pragma unroll
    for (int it = 0; it < 8; it++) {
        int slot = tid + it * 256;
        int m = slot >> 4, d8 = (slot & 15) << 3;
        const size_t go = (size_t)(r0 + m) * HID + h * HD + d8;
        *(uint4*)&sQh[m * QS + d8] = *(const uint4*)(Qh + go);
        *(uint4*)&sQl[m * QS + d8] = *(const uint4*)(Ql + go);
    }

    const int mbase = wid * 16;
    const int mrow = mbase + gid;
    const float SCALE = 0.08838834764831845f;  // 1/sqrt(128)

    float oacc[16][4];
    #pragma unroll
    for (int nf = 0; nf < 16; nf++)
        #pragma unroll
        for (int q = 0; q < 4; q++) oacc[nf][q] = 0.0f;
    float m0 = -CUDART_INF_F, m1 = -CUDART_INF_F;
    float l0 = 0.0f, l1 = 0.0f;

    const int jend = r0 + 64;
    for (int j0 = 0; j0 <= jend; j0 += 64) {
        __syncthreads();
        // K: 1024 slots/tensor; Vt: 1024 slots/tensor
        #pragma unroll
        for (int it = 0; it < 4; it++) {
            int slot = tid + it * 256;            // 0..1023
            int n = slot >> 4, d8 = (slot & 15) << 3;
            const size_t ko = (size_t)(j0 + n) * HD + d8;
            *(uint4*)&sKh[n * QS + d8] = *(const uint4*)(Kbh + ko);
            *(uint4*)&sKl[n * QS + d8] = *(const uint4*)(Kbl + ko);
            int d = slot >> 3, s8 = (slot & 7) << 3;
            const size_t vo = (size_t)d * S_LEN + j0 + s8;
            *(uint4*)&sVh[d * VS + s8] = *(const uint4*)(Vbh + vo);
            *(uint4*)&sVl[d * VS + s8] = *(const uint4*)(Vbl + vo);
        }
        __syncthreads();

        // S = Q K^T  (warp: 16 rows x 64 keys, 8 n-frags)
        float sacc[8][4];
        #pragma unroll
        for (int j = 0; j < 8; j++)
            #pragma unroll
            for (int q = 0; q < 4; q++) sacc[j][q] = 0.0f;

        #pragma unroll
        for (int kk = 0; kk < 8; kk++) {
            int k = kk * 16;
            uint32_t offA = (uint32_t)((mbase + a_r) * QS + k + a_c) * 2u;
            uint32_t qh[4], ql[4];
            ldm_x4(qh, aQh + offA);
            ldm_x4(ql, aQl + offA);
            uint32_t bh[8][2], bl[8][2];
            #pragma unroll
            for (int jp = 0; jp < 4; jp++) {
                uint32_t offB = (uint32_t)((jp * 16 + b_r) * QS + k + b_c) * 2u;
                ldm_x4(&bh[jp * 2][0], aKh + offB);
                ldm_x4(&bl[jp * 2][0], aKl + offB);
            }
            #pragma unroll
            for (int j = 0; j < 8; j++) {
                mma16816(sacc[j], qh, bh[j]);
                mma16816(sacc[j], qh, bl[j]);
                mma16816(sacc[j], ql, bh[j]);
            }
        }

        // scale + causal mask + row max
        const int row0 = r0 + mrow, row1 = row0 + 8;
        float mx0 = -CUDART_INF_F, mx1 = -CUDART_INF_F;
        #pragma unroll
        for (int j = 0; j < 8; j++) {
            int c0 = j0 + j * 8 + t4 * 2, c1 = c0 + 1;
            sacc[j][0] = (c0 > row0) ? -CUDART_INF_F : sacc[j][0] * SCALE;
            sacc[j][1] = (c1 > row0) ? -CUDART_INF_F : sacc[j][1] * SCALE;
            sacc[j][2] = (c0 > row1) ? -CUDART_INF_F : sacc[j][2] * SCALE;
            sacc[j][3] = (c1 > row1) ? -CUDART_INF_F : sacc[j][3] * SCALE;
            mx0 = fmaxf(mx0, fmaxf(sacc[j][0], sacc[j][1]));
            mx1 = fmaxf(mx1, fmaxf(sacc[j][2], sacc[j][3]));
        }
        mx0 = fmaxf(mx0, __shfl_xor_sync(0xffffffffu, mx0, 1));
        mx0 = fmaxf(mx0, __shfl_xor_sync(0xffffffffu, mx0, 2));
        mx1 = fmaxf(mx1, __shfl_xor_sync(0xffffffffu, mx1, 1));
        mx1 = fmaxf(mx1, __shfl_xor_sync(0xffffffffu, mx1, 2));

        float mn0 = fmaxf(m0, mx0), mn1 = fmaxf(m1, mx1);
        float al0 = __expf(m0 - mn0), al1 = __expf(m1 - mn1);
        m0 = mn0; m1 = mn1;

        // exp + pack P to bf16 hi/lo fragments (registers only)
        float s0 = 0.0f, s1 = 0.0f;
        uint32_t ph0[8], ph1[8], pl0[8], pl1[8];
        #pragma unroll
        for (int j = 0; j < 8; j++) {
            float p00 = __expf(sacc[j][0] - mn0);
            float p01 = __expf(sacc[j][1] - mn0);
            float p10 = __expf(sacc[j][2] - mn1);
            float p11 = __expf(sacc[j][3] - mn1);
            s0 += p00 + p01;
            s1 += p10 + p11;
            split2(p00, p01, ph0[j], pl0[j]);
            split2(p10, p11, ph1[j], pl1[j]);
        }
        s0 += __shfl_xor_sync(0xffffffffu, s0, 1);
        s0 += __shfl_xor_sync(0xffffffffu, s0, 2);
        s1 += __shfl_xor_sync(0xffffffffu, s1, 1);
        s1 += __shfl_xor_sync(0xffffffffu, s1, 2);
        l0 = l0 * al0 + s0;
        l1 = l1 * al1 + s1;

        // rescale O accumulators
        #pragma unroll
        for (int nf = 0; nf < 16; nf++) {
            oacc[nf][0] *= al0; oacc[nf][1] *= al0;
            oacc[nf][2] *= al1; oacc[nf][3] *= al1;
        }

        // O += P V
        #pragma unroll
        for (int kk = 0; kk < 4; kk++) {
            uint32_t pah[4] = {ph0[2 * kk], ph1[2 * kk],
                               ph0[2 * kk + 1], ph1[2 * kk + 1]};
            uint32_t pal[4] = {pl0[2 * kk], pl1[2 * kk],
                               pl0[2 * kk + 1], pl1[2 * kk + 1]};
            int k = kk * 16;
            #pragma unroll
            for (int np = 0; np < 8; np++) {
                uint32_t off = (uint32_t)((np * 16 + b_r) * VS + k + b_c) * 2u;
                uint32_t vh4[4], vl4[4];
                ldm_x4(vh4, aVh + off);
                ldm_x4(vl4, aVl + off);
                mma16816(oacc[2 * np],     pah, vh4);
                mma16816(oacc[2 * np],     pah, vl4);
                mma16816(oacc[2 * np],     pal, vh4);
                mma16816(oacc[2 * np + 1], pah, vh4 + 2);
                mma16816(oacc[2 * np + 1], pah, vl4 + 2);
                mma16816(oacc[2 * np + 1], pal, vh4 + 2);
            }
        }
    }

    // normalize + write out
    float inv0 = 1.0f / l0, inv1 = 1.0f / l1;
    #pragma unroll
    for (int nf = 0; nf < 16; nf++) {
        int col = h * HD + nf * 8 + t4 * 2;
        *(float2*)&O[(size_t)(r0 + mrow) * HID + col] =
            make_float2(oacc[nf][0] * inv0, oacc[nf][1] * inv0);
        *(float2*)&O[(size_t)(r0 + mrow + 8) * HID + col] =
            make_float2(oacc[nf][2] * inv1, oacc[nf][3] * inv1);
    }
}

// ---------------- launcher ----------------------------------------------------
extern "C" void kernel_launch(void* const* d_in, const int* in_sizes, int n_in,
                              void* d_out, int out_size) {
    const float* hidden  = (const float*)d_in[0];
    const float* k_cache = (const float*)d_in[1];
    const float* v_cache = (const float*)d_in[2];
    const float* Wq      = (const float*)d_in[3];
    const float* Wo      = (const float*)d_in[4];
    const int*   pos     = (const int*)d_in[5];
    float* out = (float*)d_out;

    float *qbuf, *obuf;
    __nv_bfloat16 *ah, *al, *bh, *bl, *kvh, *kvl, *vth, *vtl;
    cudaGetSymbolAddress((void**)&qbuf, g_Q);
    cudaGetSymbolAddress((void**)&obuf, g_O);
    cudaGetSymbolAddress((void**)&ah, g_Ah);
    cudaGetSymbolAddress((void**)&al, g_Al);
    cudaGetSymbolAddress((void**)&bh, g_Bh);
    cudaGetSymbolAddress((void**)&bl, g_Bl);
    cudaGetSymbolAddress((void**)&kvh, g_Kh);
    cudaGetSymbolAddress((void**)&kvl, g_Kl);
    cudaGetSymbolAddress((void**)&vth, g_Vth);
    cudaGetSymbolAddress((void**)&vtl, g_Vtl);

    const int gemm_smem = 2 * 4 * 128 * SPAD * 2;   // 147456 B
    cudaFuncSetAttribute(gemm_mma, cudaFuncAttributeMaxDynamicSharedMemorySize,
                         gemm_smem);
    const int attn_smem = (2 * 128 * QS + 2 * 64 * QS + 2 * 128 * VS) * 2; // 141312 B
    cudaFuncSetAttribute(attn_mma, cudaFuncAttributeMaxDynamicSharedMemorySize,
                         attn_smem);

    dim3 gGemm(HID / 128, S_LEN / 128);             // (32, 16)
    dim3 gT(HID / 32, HID / 32);                    // (128, 128)
    dim3 gTV(S_LEN / 32, HD / 32, NKV);             // (64, 4, 8)
    dim3 bT(32, 8);
    int convBlocks  = (S_LEN * HID / 4) / 256;      // 8192
    int convBlocksK = (NKV * S_LEN * HD / 4) / 256; // 2048

    // 0) KV pre-split (K elementwise; V transposed)
    conv_split_kernel<<<convBlocksK, 256>>>((const float4*)k_cache, (uint2*)kvh, (uint2*)kvl);
    conv_split_TV_kernel<<<gTV, bT>>>(v_cache, vth, vtl);

    // 1) Q projection
    conv_split_kernel<<<convBlocks, 256>>>((const float4*)hidden, (uint2*)ah, (uint2*)al);
    conv_split_T_kernel<<<gT, bT>>>(Wq, bh, bl);
    gemm_mma<<<gGemm, 256, gemm_smem>>>(ah, al, bh, bl, qbuf);

    // 2) RoPE + Q re-split to bf16 hi/lo
    rope_kernel<<<(S_LEN * NH * 64) / 256, 256>>>(qbuf, pos);
    conv_split_kernel<<<convBlocks, 256>>>((const float4*)qbuf, (uint2*)ah, (uint2*)al);

    // 3) Flash attention (tensor-core path, pre-split inputs)
    dim3 gAttn(S_LEN / 128, NH);
    attn_mma<<<gAttn, 256, attn_smem>>>(ah, al, kvh, kvl, vth, vtl, obuf);

    // 4) Output projection
    conv_split_kernel<<<convBlocks, 256>>>((const float4*)obuf, (uint2*)ah, (uint2*)al);
    conv_split_T_kernel<<<gT, bT>>>(Wo, bh, bl);
    gemm_mma<<<gGemm, 256, gemm_smem>>>(ah, al, bh, bl, out);
}

// round 14
// speedup vs baseline: 3.1012x; 1.0102x over previous
#include <cuda_runtime.h>
#include <cuda_bf16.h>
#include <math_constants.h>
#include <cstdint>

// Problem constants
#define S_LEN 2048
#define HID   4096
#define KDIM  4096
#define NH    32
#define NKV   8
#define HD    128
#define SPAD  72    // gemm smem row stride in bf16
#define QS    136   // attn Q/K smem row stride (d-dim, bf16)
#define VS    72    // attn Vt smem row stride (key-dim, bf16)

// ---------------- scratch (__device__ globals; no allocation APIs) -----------
__device__ float g_Q[S_LEN * HID];             // Q after proj (pre-rope, f32)
__device__ __nv_bfloat16 g_Ah[S_LEN * HID];    // split activations (hi)
__device__ __nv_bfloat16 g_Al[S_LEN * HID];    // split activations (lo)
__device__ __nv_bfloat16 g_Bh[HID * HID];      // split, transposed W (hi) [n][k]
__device__ __nv_bfloat16 g_Bl[HID * HID];      // split, transposed W (lo) [n][k]
__device__ __nv_bfloat16 g_Kh[NKV * S_LEN * HD];   // K split hi [kh][s][d]
__device__ __nv_bfloat16 g_Kl[NKV * S_LEN * HD];
__device__ __nv_bfloat16 g_Vth[NKV * HD * S_LEN];  // V split+transposed hi [kh][d][s]
__device__ __nv_bfloat16 g_Vtl[NKV * HD * S_LEN];

// ---------------- mma.sync / ldmatrix helpers (portable sm_80+ PTX) -----------
__device__ __forceinline__ void mma16816(float* d, const uint32_t* a,
                                         const uint32_t* b) {
    asm volatile(
        "mma.sync.aligned.m16n8k16.row.col.f32.bf16.bf16.f32 "
        "{%0,%1,%2,%3}, {%4,%5,%6,%7}, {%8,%9}, {%0,%1,%2,%3};"
        : "+f"(d[0]), "+f"(d[1]), "+f"(d[2]), "+f"(d[3])
        : "r"(a[0]), "r"(a[1]), "r"(a[2]), "r"(a[3]), "r"(b[0]), "r"(b[1]));
}
__device__ __forceinline__ void ldm_x4(uint32_t* r, uint32_t addr) {
    asm volatile("ldmatrix.sync.aligned.m8n8.x4.shared.b16 {%0,%1,%2,%3}, [%4];"
        : "=r"(r[0]), "=r"(r[1]), "=r"(r[2]), "=r"(r[3]) : "r"(addr));
}
__device__ __forceinline__ void cp_async16(uint32_t dst, const void* src) {
    asm volatile("cp.async.ca.shared.global [%0], [%1], 16;"
                 :: "r"(dst), "l"(src));
}
__device__ __forceinline__ uint32_t smem_u32(const void* p) {
    uint32_t a;
    asm("{ .reg .u64 t; cvta.to.shared.u64 t, %1; cvt.u32.u64 %0, t; }"
        : "=r"(a) : "l"(p));
    return a;
}
__device__ __forceinline__ void split2(float x, float y, uint32_t& h, uint32_t& l) {
    __nv_bfloat16 hx = __float2bfloat16(x), hy = __float2bfloat16(y);
    __nv_bfloat16 lx = __float2bfloat16(x - __bfloat162float(hx));
    __nv_bfloat16 ly = __float2bfloat16(y - __bfloat162float(hy));
    h = (uint32_t)__bfloat16_as_ushort(hx) | ((uint32_t)__bfloat16_as_ushort(hy) << 16);
    l = (uint32_t)__bfloat16_as_ushort(lx) | ((uint32_t)__bfloat16_as_ushort(ly) << 16);
}

// ---------------- split conversion kernels -----------------------------------
__global__ __launch_bounds__(256)
void conv_split_kernel(const float4* __restrict__ in,
                       uint2* __restrict__ hi, uint2* __restrict__ lo) {
    int i = blockIdx.x * blockDim.x + threadIdx.x;
    float4 v = in[i];
    uint32_t h01, l01, h23, l23;
    split2(v.x, v.y, h01, l01);
    split2(v.z, v.w, h23, l23);
    hi[i] = make_uint2(h01, h23);
    lo[i] = make_uint2(l01, l23);
}

__global__ __launch_bounds__(256)
void conv_split_T_kernel(const float* __restrict__ W,
                         __nv_bfloat16* __restrict__ Th,
                         __nv_bfloat16* __restrict__ Tl) {
    __shared__ float tile[32][33];
    int tx = threadIdx.x, ty = threadIdx.y;       // (32, 8)
    int n0 = blockIdx.x * 32, k0 = blockIdx.y * 32;
    #pragma unroll
    for (int i = 0; i < 4; i++)
        tile[ty + i * 8][tx] = W[(size_t)(k0 + ty + i * 8) * HID + n0 + tx];
    __syncthreads();
    #pragma unroll
    for (int i = 0; i < 4; i++) {
        float v = tile[tx][ty + i * 8];
        __nv_bfloat16 h = __float2bfloat16(v);
        __nv_bfloat16 l = __float2bfloat16(v - __bfloat162float(h));
        size_t o = (size_t)(n0 + ty + i * 8) * KDIM + k0 + tx;
        Th[o] = h; Tl[o] = l;
    }
}

// V [kh][s][d] -> Vt hi/lo [kh][d][s]
__global__ __launch_bounds__(256)
void conv_split_TV_kernel(const float* __restrict__ V,
                          __nv_bfloat16* __restrict__ Th,
                          __nv_bfloat16* __restrict__ Tl) {
    __shared__ float tile[32][33];
    int kh = blockIdx.z;
    int tx = threadIdx.x, ty = threadIdx.y;       // (32, 8)
    int s0 = blockIdx.x * 32, d0 = blockIdx.y * 32;
    const float* src = V + (size_t)kh * S_LEN * HD;
    #pragma unroll
    for (int i = 0; i < 4; i++)
        tile[ty + i * 8][tx] = src[(size_t)(s0 + ty + i * 8) * HD + d0 + tx];
    __syncthreads();
    #pragma unroll
    for (int i = 0; i < 4; i++) {
        float v = tile[tx][ty + i * 8];   // s_local=tx, d_local=ty+i*8
        __nv_bfloat16 h = __float2bfloat16(v);
        __nv_bfloat16 l = __float2bfloat16(v - __bfloat162float(h));
        size_t o = (size_t)kh * HD * S_LEN + (size_t)(d0 + ty + i * 8) * S_LEN + s0 + tx;
        Th[o] = h; Tl[o] = l;
    }
}

// ---------------- fused RoPE + split: g_Q (f32) -> ah/al (bf16) --------------
// thread handles d = 4i..4i+3 and mirrors d+64 of one (s, h).
__global__ __launch_bounds__(256)
void rope_split_kernel(const float* __restrict__ Q, const int* __restrict__ pos,
                       __nv_bfloat16* __restrict__ Oh, __nv_bfloat16* __restrict__ Ol) {
    int t = blockIdx.x * blockDim.x + threadIdx.x;   // S*NH*16 threads
    int i4 = (t & 15) << 2;          // 0,4,...,60
    int h  = (t >> 4) & 31;
    int s  = t >> 9;
    const float C = 0.14391156384599196f;            // ln(10000)/64
    float p = (float)pos[s];
    const float* base = Q + (size_t)s * HID + h * HD;
    float y1[4], y2[4];
    #pragma unroll
    for (int j = 0; j < 4; j++) {
        float ang = p * expf(-(float)(i4 + j) * C);
        float sn, cs;
        sincosf(ang, &sn, &cs);
        float x1 = base[i4 + j], x2 = base[i4 + j + 64];
        y1[j] = x1 * cs - x2 * sn;
        y2[j] = x2 * cs + x1 * sn;
    }
    uint32_t h01, l01, h23, l23;
    size_t o = (size_t)s * HID + h * HD + i4;
    split2(y1[0], y1[1], h01, l01);
    split2(y1[2], y1[3], h23, l23);
    *(uint2*)&Oh[o] = make_uint2(h01, h23);
    *(uint2*)&Ol[o] = make_uint2(l01, l23);
    split2(y2[0], y2[1], h01, l01);
    split2(y2[2], y2[3], h23, l23);
    *(uint2*)&Oh[o + 64] = make_uint2(h01, h23);
    *(uint2*)&Ol[o + 64] = make_uint2(l01, l23);
}

// ---------------- dummy (aligns gemm_mma to ncu's 6th-launch window) ---------
__global__ void dummy_kernel() {}

// ---------------- mma.sync GEMM: C = A @ W, split-bf16 3-term ----------------
__global__ __launch_bounds__(256)
void gemm_mma(const __nv_bfloat16* __restrict__ Ah, const __nv_bfloat16* __restrict__ Al,
              const __nv_bfloat16* __restrict__ Bh, const __nv_bfloat16* __restrict__ Bl,
              float* __restrict__ C) {
    extern __shared__ __align__(16) __nv_bfloat16 sm[];  // [2][4][128][SPAD]
    const uint32_t sb = smem_u32(sm);
    const int tid = threadIdx.x;
    const int wid = tid >> 5, lane = tid & 31;
    const int wm = wid >> 2, wn = wid & 3;   // 2 x 4 warp grid
    const int gid = lane >> 2, t4 = lane & 3;
    const int m0 = blockIdx.y * 128, n0 = blockIdx.x * 128;

    const int a_r = (lane & 7) + ((lane >> 3) & 1) * 8;
    const int a_c = ((lane >> 4) & 1) * 8;
    const int b_r = (lane & 7) + ((lane >> 4) & 1) * 8;
    const int b_c = ((lane >> 3) & 1) * 8;

    const __nv_bfloat16* b0p = Ah + (size_t)m0 * KDIM;
    const __nv_bfloat16* b1p = Al + (size_t)m0 * KDIM;
    const __nv_bfloat16* b2p = Bh + (size_t)n0 * KDIM;
    const __nv_bfloat16* b3p = Bl + (size_t)n0 * KDIM;

    const uint32_t TILE = 128u * SPAD * 2u;
    const uint32_t STAGE = 4u * TILE;

    float acc[4][4][4];
    #pragma unroll
    for (int i = 0; i < 4; i++)
        #pragma unroll
        for (int j = 0; j < 4; j++)
            #pragma unroll
            for (int q = 0; q < 4; q++) acc[i][j][q] = 0.0f;

    auto load_stage = [&](int c, int s) {
        const uint32_t sbase = sb + (uint32_t)s * STAGE;
        #pragma unroll
        for (int t = 0; t < 16; t++) {
            int id = tid + t * 256;
            int tile = id >> 10;
            int rem = id & 1023;
            int row = rem >> 3, j = rem & 7;
            const __nv_bfloat16* src =
                ((tile == 0) ? b0p : (tile == 1) ? b1p : (tile == 2) ? b2p : b3p)
                + (size_t)row * KDIM + c * 64 + j * 8;
            uint32_t dst = sbase + (uint32_t)tile * TILE
                         + ((uint32_t)row * SPAD + (uint32_t)j * 8) * 2u;
            cp_async16(dst, src);
        }
        asm volatile("cp.async.commit_group;" ::: "memory");
    };

    const int NC = KDIM / 64;
    load_stage(0, 0);

    for (int c = 0; c < NC; c++) {
        if (c + 1 < NC) {
            load_stage(c + 1, (c + 1) & 1);
            asm volatile("cp.async.wait_group 1;" ::: "memory");
        } else {
            asm volatile("cp.async.wait_group 0;" ::: "memory");
        }
        __syncthreads();

        const uint32_t sAh = sb + (uint32_t)(c & 1) * STAGE;
        const uint32_t sAl = sAh + TILE;
        const uint32_t sBh = sAl + TILE;
        const uint32_t sBl = sBh + TILE;

        #pragma unroll
        for (int ks = 0; ks < 4; ks++) {
            const int k = ks * 16;
            uint32_t ah[4][4], al[4][4];
            #pragma unroll
            for (int mf = 0; mf < 4; mf++) {
                uint32_t off = (uint32_t)((wm * 64 + mf * 16 + a_r) * SPAD + k + a_c) * 2u;
                ldm_x4(ah[mf], sAh + off);
                ldm_x4(al[mf], sAl + off);
            }
            uint32_t bh[4][2], bl[4][2];
            #pragma unroll
            for (int np = 0; np < 2; np++) {
                uint32_t off = (uint32_t)((wn * 32 + np * 16 + b_r) * SPAD + k + b_c) * 2u;
                ldm_x4(&bh[np * 2][0], sBh + off);
                ldm_x4(&bl[np * 2][0], sBl + off);
            }
            #pragma unroll
            for (int mf = 0; mf < 4; mf++)
                #pragma unroll
                for (int nf = 0; nf < 4; nf++) {
                    mma16816(acc[mf][nf], ah[mf], bh[nf]);
                    mma16816(acc[mf][nf], ah[mf], bl[nf]);
                    mma16816(acc[mf][nf], al[mf], bh[nf]);
                }
        }
        __syncthreads();
    }

    #pragma unroll
    for (int mf = 0; mf < 4; mf++)
        #pragma unroll
        for (int nf = 0; nf < 4; nf++) {
            int row = m0 + wm * 64 + mf * 16 + gid;
            int col = n0 + wn * 32 + nf * 8 + t4 * 2;
            float2 v0 = make_float2(acc[mf][nf][0], acc[mf][nf][1]);
            float2 v1 = make_float2(acc[mf][nf][2], acc[mf][nf][3]);
            *(float2*)&C[(size_t)row * HID + col]       = v0;
            *(float2*)&C[(size_t)(row + 8) * HID + col] = v1;
        }
}

// ---------------- Flash attention via mma.sync (causal, GQA) ------------------
// Pre-split bf16 inputs; ldmatrix fragment loads; P in registers.
// Output written PRE-SPLIT (bf16 hi/lo) into the same Q-split buffers — safe:
// each CTA overwrites exactly the (rows, head)-slice it alone consumed as Q.
__global__ __launch_bounds__(256)
void attn_mma(const __nv_bfloat16* __restrict__ Qh, const __nv_bfloat16* __restrict__ Ql,
              const __nv_bfloat16* __restrict__ Kh, const __nv_bfloat16* __restrict__ Kl,
              const __nv_bfloat16* __restrict__ Vth, const __nv_bfloat16* __restrict__ Vtl,
              __nv_bfloat16* __restrict__ Oh, __nv_bfloat16* __restrict__ Ol) {
    extern __shared__ __align__(16) __nv_bfloat16 sa[];
    __nv_bfloat16* sQh = sa;                 // [128][QS]
    __nv_bfloat16* sQl = sQh + 128 * QS;
    __nv_bfloat16* sKh = sQl + 128 * QS;     // [64][QS]
    __nv_bfloat16* sKl = sKh + 64 * QS;
    __nv_bfloat16* sVh = sKl + 64 * QS;      // [128 d][VS]
    __nv_bfloat16* sVl = sVh + 128 * VS;
    const uint32_t sbase = smem_u32(sa);
    const uint32_t aQh = sbase;
    const uint32_t aQl = aQh + 128u * QS * 2u;
    const uint32_t aKh = aQl + 128u * QS * 2u;
    const uint32_t aKl = aKh + 64u * QS * 2u;
    const uint32_t aVh = aKl + 64u * QS * 2u;
    const uint32_t aVl = aVh + 128u * VS * 2u;

    const int tid = threadIdx.x;
    const int wid = tid >> 5, lane = tid & 31;
    const int gid = lane >> 2, t4 = lane & 3;
    const int a_r = (lane & 7) + ((lane >> 3) & 1) * 8;
    const int a_c = ((lane >> 4) & 1) * 8;
    const int b_r = (lane & 7) + ((lane >> 4) & 1) * 8;
    const int b_c = ((lane >> 3) & 1) * 8;

    const int qt = (int)gridDim.x - 1 - (int)blockIdx.x;  // heavy tiles first
    const int h = blockIdx.y;
    const int r0 = qt * 128;
    const int khd = h >> 2;
    const __nv_bfloat16* Kbh = Kh + (size_t)khd * S_LEN * HD;
    const __nv_bfloat16* Kbl = Kl + (size_t)khd * S_LEN * HD;
    const __nv_bfloat16* Vbh = Vth + (size_t)khd * HD * S_LEN;
    const __nv_bfloat16* Vbl = Vtl + (size_t)khd * HD * S_LEN;

    // Q tile: bf16 hi/lo direct copies
    #pragma unroll
    for (int it = 0; it < 8; it++) {
        int slot = tid + it * 256;
        int m = slot >> 4, d8 = (slot & 15) << 3;
        const size_t go = (size_t)(r0 + m) * HID + h * HD + d8;
        *(uint4*)&sQh[m * QS + d8] = *(const uint4*)(Qh + go);
        *(uint4*)&sQl[m * QS + d8] = *(const uint4*)(Ql + go);
    }

    const int mbase = wid * 16;
    const int mrow = mbase + gid;
    const float SCALE = 0.08838834764831845f;  // 1/sqrt(128)

    float oacc[16][4];
    #pragma unroll
    for (int nf = 0; nf < 16; nf++)
        #pragma unroll
        for (int q = 0; q < 4; q++) oacc[nf][q] = 0.0f;
    float m0 = -CUDART_INF_F, m1 = -CUDART_INF_F;
    float l0 = 0.0f, l1 = 0.0f;

    const int jend = r0 + 64;
    for (int j0 = 0; j0 <= jend; j0 += 64) {
        __syncthreads();
        #pragma unroll
        for (int it = 0; it < 4; it++) {
            int slot = tid + it * 256;            // 0..1023
            int n = slot >> 4, d8 = (slot & 15) << 3;
            const size_t ko = (size_t)(j0 + n) * HD + d8;
            *(uint4*)&sKh[n * QS + d8] = *(const uint4*)(Kbh + ko);
            *(uint4*)&sKl[n * QS + d8] = *(const uint4*)(Kbl + ko);
            int d = slot >> 3, s8 = (slot & 7) << 3;
            const size_t vo = (size_t)d * S_LEN + j0 + s8;
            *(uint4*)&sVh[d * VS + s8] = *(const uint4*)(Vbh + vo);
            *(uint4*)&sVl[d * VS + s8] = *(const uint4*)(Vbl + vo);
        }
        __syncthreads();

        // S = Q K^T
        float sacc[8][4];
        #pragma unroll
        for (int j = 0; j < 8; j++)
            #pragma unroll
            for (int q = 0; q < 4; q++) sacc[j][q] = 0.0f;

        #pragma unroll
        for (int kk = 0; kk < 8; kk++) {
            int k = kk * 16;
            uint32_t offA = (uint32_t)((mbase + a_r) * QS + k + a_c) * 2u;
            uint32_t qh[4], ql[4];
            ldm_x4(qh, aQh + offA);
            ldm_x4(ql, aQl + offA);
            uint32_t bh[8][2], bl[8][2];
            #pragma unroll
            for (int jp = 0; jp < 4; jp++) {
                uint32_t offB = (uint32_t)((jp * 16 + b_r) * QS + k + b_c) * 2u;
                ldm_x4(&bh[jp * 2][0], aKh + offB);
                ldm_x4(&bl[jp * 2][0], aKl + offB);
            }
            #pragma unroll
            for (int j = 0; j < 8; j++) {
                mma16816(sacc[j], qh, bh[j]);
                mma16816(sacc[j], qh, bl[j]);
                mma16816(sacc[j], ql, bh[j]);
            }
        }

        // scale + causal mask + row max
        const int row0 = r0 + mrow, row1 = row0 + 8;
        float mx0 = -CUDART_INF_F, mx1 = -CUDART_INF_F;
        #pragma unroll
        for (int j = 0; j < 8; j++) {
            int c0 = j0 + j * 8 + t4 * 2, c1 = c0 + 1;
            sacc[j][0] = (c0 > row0) ? -CUDART_INF_F : sacc[j][0] * SCALE;
            sacc[j][1] = (c1 > row0) ? -CUDART_INF_F : sacc[j][1] * SCALE;
            sacc[j][2] = (c0 > row1) ? -CUDART_INF_F : sacc[j][2] * SCALE;
            sacc[j][3] = (c1 > row1) ? -CUDART_INF_F : sacc[j][3] * SCALE;
            mx0 = fmaxf(mx0, fmaxf(sacc[j][0], sacc[j][1]));
            mx1 = fmaxf(mx1, fmaxf(sacc[j][2], sacc[j][3]));
        }
        mx0 = fmaxf(mx0, __shfl_xor_sync(0xffffffffu, mx0, 1));
        mx0 = fmaxf(mx0, __shfl_xor_sync(0xffffffffu, mx0, 2));
        mx1 = fmaxf(mx1, __shfl_xor_sync(0xffffffffu, mx1, 1));
        mx1 = fmaxf(mx1, __shfl_xor_sync(0xffffffffu, mx1, 2));

        float mn0 = fmaxf(m0, mx0), mn1 = fmaxf(m1, mx1);
        float al0 = __expf(m0 - mn0), al1 = __expf(m1 - mn1);
        m0 = mn0; m1 = mn1;

        // exp + pack P to bf16 hi/lo fragments (registers only)
        float s0 = 0.0f, s1 = 0.0f;
        uint32_t ph0[8], ph1[8], pl0[8], pl1[8];
        #pragma unroll
        for (int j = 0; j < 8; j++) {
            float p00 = __expf(sacc[j][0] - mn0);
            float p01 = __expf(sacc[j][1] - mn0);
            float p10 = __expf(sacc[j][2] - mn1);
            float p11 = __expf(sacc[j][3] - mn1);
            s0 += p00 + p01;
            s1 += p10 + p11;
            split2(p00, p01, ph0[j], pl0[j]);
            split2(p10, p11, ph1[j], pl1[j]);
        }
        s0 += __shfl_xor_sync(0xffffffffu, s0, 1);
        s0 += __shfl_xor_sync(0xffffffffu, s0, 2);
        s1 += __shfl_xor_sync(0xffffffffu, s1, 1);
        s1 += __shfl_xor_sync(0xffffffffu, s1, 2);
        l0 = l0 * al0 + s0;
        l1 = l1 * al1 + s1;

        // rescale O accumulators
        #pragma unroll
        for (int nf = 0; nf < 16; nf++) {
            oacc[nf][0] *= al0; oacc[nf][1] *= al0;
            oacc[nf][2] *= al1; oacc[nf][3] *= al1;
        }

        // O += P V
        #pragma unroll
        for (int kk = 0; kk < 4; kk++) {
            uint32_t pah[4] = {ph0[2 * kk], ph1[2 * kk],
                               ph0[2 * kk + 1], ph1[2 * kk + 1]};
            uint32_t pal[4] = {pl0[2 * kk], pl1[2 * kk],
                               pl0[2 * kk + 1], pl1[2 * kk + 1]};
            int k = kk * 16;
            #pragma unroll
            for (int np = 0; np < 8; np++) {
                uint32_t off = (uint32_t)((np * 16 + b_r) * VS + k + b_c) * 2u;
                uint32_t vh4[4], vl4[4];
                ldm_x4(vh4, aVh + off);
                ldm_x4(vl4, aVl + off);
                mma16816(oacc[2 * np],     pah, vh4);
                mma16816(oacc[2 * np],     pah, vl4);
                mma16816(oacc[2 * np],     pal, vh4);
                mma16816(oacc[2 * np + 1], pah, vh4 + 2);
                mma16816(oacc[2 * np + 1], pah, vl4 + 2);
                mma16816(oacc[2 * np + 1], pal, vh4 + 2);
            }
        }
    }

    // normalize + split + write (bf16 hi/lo, ready for O-projection)
    float inv0 = 1.0f / l0, inv1 = 1.0f / l1;
    #pragma unroll
    for (int nf = 0; nf < 16; nf++) {
        int col = h * HD + nf * 8 + t4 * 2;
        uint32_t hh, ll;
        size_t o0 = (size_t)(r0 + mrow) * HID + col;
        split2(oacc[nf][0] * inv0, oacc[nf][1] * inv0, hh, ll);
        *(uint32_t*)&Oh[o0] = hh;
        *(uint32_t*)&Ol[o0] = ll;
        size_t o1 = (size_t)(r0 + mrow + 8) * HID + col;
        split2(oacc[nf][2] * inv1, oacc[nf][3] * inv1, hh, ll);
        *(uint32_t*)&Oh[o1] = hh;
        *(uint32_t*)&Ol[o1] = ll;
    }
}

// ---------------- launcher ----------------------------------------------------
extern "C" void kernel_launch(void* const* d_in, const int* in_sizes, int n_in,
                              void* d_out, int out_size) {
    const float* hidden  = (const float*)d_in[0];
    const float* k_cache = (const float*)d_in[1];
    const float* v_cache = (const float*)d_in[2];
    const float* Wq      = (const float*)d_in[3];
    const float* Wo      = (const float*)d_in[4];
    const int*   pos     = (const int*)d_in[5];
    float* out = (float*)d_out;

    float *qbuf;
    __nv_bfloat16 *ah, *al, *bh, *bl, *kvh, *kvl, *vth, *vtl;
    cudaGetSymbolAddress((void**)&qbuf, g_Q);
    cudaGetSymbolAddress((void**)&ah, g_Ah);
    cudaGetSymbolAddress((void**)&al, g_Al);
    cudaGetSymbolAddress((void**)&bh, g_Bh);
    cudaGetSymbolAddress((void**)&bl, g_Bl);
    cudaGetSymbolAddress((void**)&kvh, g_Kh);
    cudaGetSymbolAddress((void**)&kvl, g_Kl);
    cudaGetSymbolAddress((void**)&vth, g_Vth);
    cudaGetSymbolAddress((void**)&vtl, g_Vtl);

    const int gemm_smem = 2 * 4 * 128 * SPAD * 2;   // 147456 B
    cudaFuncSetAttribute(gemm_mma, cudaFuncAttributeMaxDynamicSharedMemorySize,
                         gemm_smem);
    const int attn_smem = (2 * 128 * QS + 2 * 64 * QS + 2 * 128 * VS) * 2; // 141312 B
    cudaFuncSetAttribute(attn_mma, cudaFuncAttributeMaxDynamicSharedMemorySize,
                         attn_smem);

    dim3 gGemm(HID / 128, S_LEN / 128);             // (32, 16)
    dim3 gT(HID / 32, HID / 32);                    // (128, 128)
    dim3 gTV(S_LEN / 32, HD / 32, NKV);             // (64, 4, 8)
    dim3 bT(32, 8);
    int convBlocks  = (S_LEN * HID / 4) / 256;      // 8192
    int convBlocksK = (NKV * S_LEN * HD / 4) / 256; // 2048

    // Launch order fixed so gemm_mma is launch #6 (ncu -s 5 -c 1 window).
    // 1) K pre-split
    conv_split_kernel<<<convBlocksK, 256>>>((const float4*)k_cache, (uint2*)kvh, (uint2*)kvl);
    // 2) V pre-split + transpose
    conv_split_TV_kernel<<<gTV, bT>>>(v_cache, vth, vtl);
    // 3) hidden split
    conv_split_kernel<<<convBlocks, 256>>>((const float4*)hidden, (uint2*)ah, (uint2*)al);
    // 4) Wq split+T
    conv_split_T_kernel<<<gT, bT>>>(Wq, bh, bl);
    // 5) dummy (profiling alignment)
    dummy_kernel<<<1, 32>>>();
    // 6) Q projection  <- profiled
    gemm_mma<<<gGemm, 256, gemm_smem>>>(ah, al, bh, bl, qbuf);
    // 7) fused RoPE + split (g_Q -> ah/al)
    rope_split_kernel<<<(S_LEN * NH * 16) / 256, 256>>>(qbuf, pos, ah, al);
    // 8) flash attention; output pre-split into ah/al (in-place per-CTA slice)
    dim3 gAttn(S_LEN / 128, NH);
    attn_mma<<<gAttn, 256, attn_smem>>>(ah, al, kvh, kvl, vth, vtl, ah, al);
    // 9) Wo split+T
    conv_split_T_kernel<<<gT, bT>>>(Wo, bh, bl);
    // 10) O projection
    gemm_mma<<<gGemm, 256, gemm_smem>>>(ah, al, bh, bl, out);
}

// round 17
// speedup vs baseline: 3.1598x; 1.0189x over previous
#include <cuda_runtime.h>
#include <cuda_bf16.h>
#include <math_constants.h>
#include <cstdint>

// Problem constants
#define S_LEN 2048
#define HID   4096
#define KDIM  4096
#define NH    32
#define NKV   8
#define HD    128
#define SPAD  72    // gemm smem row stride in bf16
#define QS    136   // attn Q/K smem row stride (d-dim, bf16)
#define VS    72    // attn Vt smem row stride (key-dim, bf16)

// ---------------- scratch (__device__ globals; no allocation APIs) -----------
__device__ float g_Q[S_LEN * HID];             // Q after proj (pre-rope, f32)
__device__ __nv_bfloat16 g_Ah[S_LEN * HID];    // split activations (hi)
__device__ __nv_bfloat16 g_Al[S_LEN * HID];    // split activations (lo)
__device__ __nv_bfloat16 g_Bh[HID * HID];      // split, transposed W (hi) [n][k]
__device__ __nv_bfloat16 g_Bl[HID * HID];      // split, transposed W (lo) [n][k]
__device__ __nv_bfloat16 g_Kh[NKV * S_LEN * HD];   // K split hi [kh][s][d]
__device__ __nv_bfloat16 g_Kl[NKV * S_LEN * HD];
__device__ __nv_bfloat16 g_Vth[NKV * HD * S_LEN];  // V split+transposed hi [kh][d][s]
__device__ __nv_bfloat16 g_Vtl[NKV * HD * S_LEN];

// ---------------- mma.sync / ldmatrix helpers (portable sm_80+ PTX) -----------
__device__ __forceinline__ void mma16816(float* d, const uint32_t* a,
                                         const uint32_t* b) {
    asm volatile(
        "mma.sync.aligned.m16n8k16.row.col.f32.bf16.bf16.f32 "
        "{%0,%1,%2,%3}, {%4,%5,%6,%7}, {%8,%9}, {%0,%1,%2,%3};"
        : "+f"(d[0]), "+f"(d[1]), "+f"(d[2]), "+f"(d[3])
        : "r"(a[0]), "r"(a[1]), "r"(a[2]), "r"(a[3]), "r"(b[0]), "r"(b[1]));
}
__device__ __forceinline__ void ldm_x4(uint32_t* r, uint32_t addr) {
    asm volatile("ldmatrix.sync.aligned.m8n8.x4.shared.b16 {%0,%1,%2,%3}, [%4];"
        : "=r"(r[0]), "=r"(r[1]), "=r"(r[2]), "=r"(r[3]) : "r"(addr));
}
__device__ __forceinline__ void cp_async16(uint32_t dst, const void* src) {
    asm volatile("cp.async.ca.shared.global [%0], [%1], 16;"
                 :: "r"(dst), "l"(src));
}
__device__ __forceinline__ uint32_t smem_u32(const void* p) {
    uint32_t a;
    asm("{ .reg .u64 t; cvta.to.shared.u64 t, %1; cvt.u32.u64 %0, t; }"
        : "=r"(a) : "l"(p));
    return a;
}
__device__ __forceinline__ void split2(float x, float y, uint32_t& h, uint32_t& l) {
    __nv_bfloat16 hx = __float2bfloat16(x), hy = __float2bfloat16(y);
    __nv_bfloat16 lx = __float2bfloat16(x - __bfloat162float(hx));
    __nv_bfloat16 ly = __float2bfloat16(y - __bfloat162float(hy));
    h = (uint32_t)__bfloat16_as_ushort(hx) | ((uint32_t)__bfloat16_as_ushort(hy) << 16);
    l = (uint32_t)__bfloat16_as_ushort(lx) | ((uint32_t)__bfloat16_as_ushort(ly) << 16);
}

// ---------------- split conversion kernels -----------------------------------
__global__ __launch_bounds__(256)
void conv_split_kernel(const float4* __restrict__ in,
                       uint2* __restrict__ hi, uint2* __restrict__ lo) {
    int i = blockIdx.x * blockDim.x + threadIdx.x;
    float4 v = in[i];
    uint32_t h01, l01, h23, l23;
    split2(v.x, v.y, h01, l01);
    split2(v.z, v.w, h23, l23);
    hi[i] = make_uint2(h01, h23);
    lo[i] = make_uint2(l01, l23);
}

__global__ __launch_bounds__(256)
void conv_split_T_kernel(const float* __restrict__ W,
                         __nv_bfloat16* __restrict__ Th,
                         __nv_bfloat16* __restrict__ Tl) {
    __shared__ float tile[32][33];
    int tx = threadIdx.x, ty = threadIdx.y;       // (32, 8)
    int n0 = blockIdx.x * 32, k0 = blockIdx.y * 32;
    #pragma unroll
    for (int i = 0; i < 4; i++)
        tile[ty + i * 8][tx] = W[(size_t)(k0 + ty + i * 8) * HID + n0 + tx];
    __syncthreads();
    #pragma unroll
    for (int i = 0; i < 4; i++) {
        float v = tile[tx][ty + i * 8];
        __nv_bfloat16 h = __float2bfloat16(v);
        __nv_bfloat16 l = __float2bfloat16(v - __bfloat162float(h));
        size_t o = (size_t)(n0 + ty + i * 8) * KDIM + k0 + tx;
        Th[o] = h; Tl[o] = l;
    }
}

// V [kh][s][d] -> Vt hi/lo [kh][d][s]
__global__ __launch_bounds__(256)
void conv_split_TV_kernel(const float* __restrict__ V,
                          __nv_bfloat16* __restrict__ Th,
                          __nv_bfloat16* __restrict__ Tl) {
    __shared__ float tile[32][33];
    int kh = blockIdx.z;
    int tx = threadIdx.x, ty = threadIdx.y;       // (32, 8)
    int s0 = blockIdx.x * 32, d0 = blockIdx.y * 32;
    const float* src = V + (size_t)kh * S_LEN * HD;
    #pragma unroll
    for (int i = 0; i < 4; i++)
        tile[ty + i * 8][tx] = src[(size_t)(s0 + ty + i * 8) * HD + d0 + tx];
    __syncthreads();
    #pragma unroll
    for (int i = 0; i < 4; i++) {
        float v = tile[tx][ty + i * 8];   // s_local=tx, d_local=ty+i*8
        __nv_bfloat16 h = __float2bfloat16(v);
        __nv_bfloat16 l = __float2bfloat16(v - __bfloat162float(h));
        size_t o = (size_t)kh * HD * S_LEN + (size_t)(d0 + ty + i * 8) * S_LEN + s0 + tx;
        Th[o] = h; Tl[o] = l;
    }
}

// ---------------- fused RoPE + split: g_Q (f32) -> ah/al (bf16) --------------
__global__ __launch_bounds__(256)
void rope_split_kernel(const float* __restrict__ Q, const int* __restrict__ pos,
                       __nv_bfloat16* __restrict__ Oh, __nv_bfloat16* __restrict__ Ol) {
    int t = blockIdx.x * blockDim.x + threadIdx.x;   // S*NH*16 threads
    int i4 = (t & 15) << 2;          // 0,4,...,60
    int h  = (t >> 4) & 31;
    int s  = t >> 9;
    const float C = 0.14391156384599196f;            // ln(10000)/64
    float p = (float)pos[s];
    const float* base = Q + (size_t)s * HID + h * HD;
    float y1[4], y2[4];
    #pragma unroll
    for (int j = 0; j < 4; j++) {
        float ang = p * expf(-(float)(i4 + j) * C);
        float sn, cs;
        sincosf(ang, &sn, &cs);
        float x1 = base[i4 + j], x2 = base[i4 + j + 64];
        y1[j] = x1 * cs - x2 * sn;
        y2[j] = x2 * cs + x1 * sn;
    }
    uint32_t h01, l01, h23, l23;
    size_t o = (size_t)s * HID + h * HD + i4;
    split2(y1[0], y1[1], h01, l01);
    split2(y1[2], y1[3], h23, l23);
    *(uint2*)&Oh[o] = make_uint2(h01, h23);
    *(uint2*)&Ol[o] = make_uint2(l01, l23);
    split2(y2[0], y2[1], h01, l01);
    split2(y2[2], y2[3], h23, l23);
    *(uint2*)&Oh[o + 64] = make_uint2(h01, h23);
    *(uint2*)&Ol[o + 64] = make_uint2(l01, l23);
}

// ---------------- mma.sync GEMM: C = A @ W, split-bf16 3-term ----------------
__global__ __launch_bounds__(256)
void gemm_mma(const __nv_bfloat16* __restrict__ Ah, const __nv_bfloat16* __restrict__ Al,
              const __nv_bfloat16* __restrict__ Bh, const __nv_bfloat16* __restrict__ Bl,
              float* __restrict__ C) {
    extern __shared__ __align__(16) __nv_bfloat16 sm[];  // [2][4][128][SPAD]
    const uint32_t sb = smem_u32(sm);
    const int tid = threadIdx.x;
    const int wid = tid >> 5, lane = tid & 31;
    const int wm = wid >> 2, wn = wid & 3;   // 2 x 4 warp grid
    const int gid = lane >> 2, t4 = lane & 3;
    const int m0 = blockIdx.y * 128, n0 = blockIdx.x * 128;

    const int a_r = (lane & 7) + ((lane >> 3) & 1) * 8;
    const int a_c = ((lane >> 4) & 1) * 8;
    const int b_r = (lane & 7) + ((lane >> 4) & 1) * 8;
    const int b_c = ((lane >> 3) & 1) * 8;

    const __nv_bfloat16* b0p = Ah + (size_t)m0 * KDIM;
    const __nv_bfloat16* b1p = Al + (size_t)m0 * KDIM;
    const __nv_bfloat16* b2p = Bh + (size_t)n0 * KDIM;
    const __nv_bfloat16* b3p = Bl + (size_t)n0 * KDIM;

    const uint32_t TILE = 128u * SPAD * 2u;
    const uint32_t STAGE = 4u * TILE;

    float acc[4][4][4];
    #pragma unroll
    for (int i = 0; i < 4; i++)
        #pragma unroll
        for (int j = 0; j < 4; j++)
            #pragma unroll
            for (int q = 0; q < 4; q++) acc[i][j][q] = 0.0f;

    auto load_stage = [&](int c, int s) {
        const uint32_t sbase = sb + (uint32_t)s * STAGE;
        #pragma unroll
        for (int t = 0; t < 16; t++) {
            int id = tid + t * 256;
            int tile = id >> 10;
            int rem = id & 1023;
            int row = rem >> 3, j = rem & 7;
            const __nv_bfloat16* src =
                ((tile == 0) ? b0p : (tile == 1) ? b1p : (tile == 2) ? b2p : b3p)
                + (size_t)row * KDIM + c * 64 + j * 8;
            uint32_t dst = sbase + (uint32_t)tile * TILE
                         + ((uint32_t)row * SPAD + (uint32_t)j * 8) * 2u;
            cp_async16(dst, src);
        }
        asm volatile("cp.async.commit_group;" ::: "memory");
    };

    const int NC = KDIM / 64;
    load_stage(0, 0);

    for (int c = 0; c < NC; c++) {
        if (c + 1 < NC) {
            load_stage(c + 1, (c + 1) & 1);
            asm volatile("cp.async.wait_group 1;" ::: "memory");
        } else {
            asm volatile("cp.async.wait_group 0;" ::: "memory");
        }
        __syncthreads();

        const uint32_t sAh = sb + (uint32_t)(c & 1) * STAGE;
        const uint32_t sAl = sAh + TILE;
        const uint32_t sBh = sAl + TILE;
        const uint32_t sBl = sBh + TILE;

        #pragma unroll
        for (int ks = 0; ks < 4; ks++) {
            const int k = ks * 16;
            uint32_t ah[4][4], al[4][4];
            #pragma unroll
            for (int mf = 0; mf < 4; mf++) {
                uint32_t off = (uint32_t)((wm * 64 + mf * 16 + a_r) * SPAD + k + a_c) * 2u;
                ldm_x4(ah[mf], sAh + off);
                ldm_x4(al[mf], sAl + off);
            }
            uint32_t bh[4][2], bl[4][2];
            #pragma unroll
            for (int np = 0; np < 2; np++) {
                uint32_t off = (uint32_t)((wn * 32 + np * 16 + b_r) * SPAD + k + b_c) * 2u;
                ldm_x4(&bh[np * 2][0], sBh + off);
                ldm_x4(&bl[np * 2][0], sBl + off);
            }
            #pragma unroll
            for (int mf = 0; mf < 4; mf++)
                #pragma unroll
                for (int nf = 0; nf < 4; nf++) {
                    mma16816(acc[mf][nf], ah[mf], bh[nf]);
                    mma16816(acc[mf][nf], ah[mf], bl[nf]);
                    mma16816(acc[mf][nf], al[mf], bh[nf]);
                }
        }
        __syncthreads();
    }

    #pragma unroll
    for (int mf = 0; mf < 4; mf++)
        #pragma unroll
        for (int nf = 0; nf < 4; nf++) {
            int row = m0 + wm * 64 + mf * 16 + gid;
            int col = n0 + wn * 32 + nf * 8 + t4 * 2;
            float2 v0 = make_float2(acc[mf][nf][0], acc[mf][nf][1]);
            float2 v1 = make_float2(acc[mf][nf][2], acc[mf][nf][3]);
            *(float2*)&C[(size_t)row * HID + col]       = v0;
            *(float2*)&C[(size_t)(row + 8) * HID + col] = v1;
        }
}

// ---------------- Flash attention via mma.sync (causal, GQA) ------------------
// Pre-split bf16 inputs; ldmatrix frags; P in registers; K/V double-buffered
// via cp.async (2 stages). Output written pre-split into the Q buffers (safe:
// each CTA overwrites exactly the slice it alone consumed as Q).
#define KV_KBYTES (64u * QS * 2u)     // 17408 per K tensor
#define KV_VBYTES (128u * VS * 2u)    // 18432 per V tensor
#define KV_STAGE  (2u * KV_KBYTES + 2u * KV_VBYTES)  // 71680
__global__ __launch_bounds__(256)
void attn_mma(const __nv_bfloat16* __restrict__ Qh, const __nv_bfloat16* __restrict__ Ql,
              const __nv_bfloat16* __restrict__ Kh, const __nv_bfloat16* __restrict__ Kl,
              const __nv_bfloat16* __restrict__ Vth, const __nv_bfloat16* __restrict__ Vtl,
              __nv_bfloat16* __restrict__ Oh, __nv_bfloat16* __restrict__ Ol) {
    extern __shared__ __align__(16) __nv_bfloat16 sa[];
    __nv_bfloat16* sQh = sa;                 // [128][QS]
    __nv_bfloat16* sQl = sQh + 128 * QS;
    const uint32_t sbase = smem_u32(sa);
    const uint32_t aQh = sbase;
    const uint32_t aQl = aQh + 128u * QS * 2u;
    const uint32_t kvb = aQl + 128u * QS * 2u;   // K/V stages base

    const int tid = threadIdx.x;
    const int wid = tid >> 5, lane = tid & 31;
    const int gid = lane >> 2, t4 = lane & 3;
    const int a_r = (lane & 7) + ((lane >> 3) & 1) * 8;
    const int a_c = ((lane >> 4) & 1) * 8;
    const int b_r = (lane & 7) + ((lane >> 4) & 1) * 8;
    const int b_c = ((lane >> 3) & 1) * 8;

    const int qt = (int)gridDim.x - 1 - (int)blockIdx.x;  // heavy tiles first
    const int h = blockIdx.y;
    const int r0 = qt * 128;
    const int khd = h >> 2;
    const __nv_bfloat16* Kbh = Kh + (size_t)khd * S_LEN * HD;
    const __nv_bfloat16* Kbl = Kl + (size_t)khd * S_LEN * HD;
    const __nv_bfloat16* Vbh = Vth + (size_t)khd * HD * S_LEN;
    const __nv_bfloat16* Vbl = Vtl + (size_t)khd * HD * S_LEN;

    auto load_kv = [&](int j0, int s) {
        const uint32_t st = kvb + (uint32_t)s * KV_STAGE;
        #pragma unroll
        for (int it = 0; it < 4; it++) {
            int slot = tid + it * 256;                // 0..1023
            int n = slot >> 4, d8 = (slot & 15) << 3;
            const size_t ko = (size_t)(j0 + n) * HD + d8;
            uint32_t koff = (uint32_t)(n * QS + d8) * 2u;
            cp_async16(st + koff, Kbh + ko);
            cp_async16(st + KV_KBYTES + koff, Kbl + ko);
            int d = slot >> 3, s8 = (slot & 7) << 3;
            const size_t vo = (size_t)d * S_LEN + j0 + s8;
            uint32_t voff = (uint32_t)(d * VS + s8) * 2u;
            cp_async16(st + 2u * KV_KBYTES + voff, Vbh + vo);
            cp_async16(st + 2u * KV_KBYTES + KV_VBYTES + voff, Vbl + vo);
        }
        asm volatile("cp.async.commit_group;" ::: "memory");
    };

    // Q tile: bf16 hi/lo direct copies
    #pragma unroll
    for (int it = 0; it < 8; it++) {
        int slot = tid + it * 256;
        int m = slot >> 4, d8 = (slot & 15) << 3;
        const size_t go = (size_t)(r0 + m) * HID + h * HD + d8;
        *(uint4*)&sQh[m * QS + d8] = *(const uint4*)(Qh + go);
        *(uint4*)&sQl[m * QS + d8] = *(const uint4*)(Ql + go);
    }

    const int mbase = wid * 16;
    const int mrow = mbase + gid;
    const float SCALE = 0.08838834764831845f;  // 1/sqrt(128)

    float oacc[16][4];
    #pragma unroll
    for (int nf = 0; nf < 16; nf++)
        #pragma unroll
        for (int q = 0; q < 4; q++) oacc[nf][q] = 0.0f;
    float m0 = -CUDART_INF_F, m1 = -CUDART_INF_F;
    float l0 = 0.0f, l1 = 0.0f;

    const int NIT = 2 * qt + 2;
    load_kv(0, 0);

    for (int itr = 0; itr < NIT; itr++) {
        const int j0 = itr * 64;
        if (itr + 1 < NIT) {
            load_kv((itr + 1) * 64, (itr + 1) & 1);
            asm volatile("cp.async.wait_group 1;" ::: "memory");
        } else {
            asm volatile("cp.async.wait_group 0;" ::: "memory");
        }
        __syncthreads();

        const uint32_t st = kvb + (uint32_t)(itr & 1) * KV_STAGE;
        const uint32_t aKh = st;
        const uint32_t aKl = st + KV_KBYTES;
        const uint32_t aVh = st + 2u * KV_KBYTES;
        const uint32_t aVl = aVh + KV_VBYTES;

        // S = Q K^T
        float sacc[8][4];
        #pragma unroll
        for (int j = 0; j < 8; j++)
            #pragma unroll
            for (int q = 0; q < 4; q++) sacc[j][q] = 0.0f;

        #pragma unroll
        for (int kk = 0; kk < 8; kk++) {
            int k = kk * 16;
            uint32_t offA = (uint32_t)((mbase + a_r) * QS + k + a_c) * 2u;
            uint32_t qh[4], ql[4];
            ldm_x4(qh, aQh + offA);
            ldm_x4(ql, aQl + offA);
            uint32_t bh[8][2], bl[8][2];
            #pragma unroll
            for (int jp = 0; jp < 4; jp++) {
                uint32_t offB = (uint32_t)((jp * 16 + b_r) * QS + k + b_c) * 2u;
                ldm_x4(&bh[jp * 2][0], aKh + offB);
                ldm_x4(&bl[jp * 2][0], aKl + offB);
            }
            #pragma unroll
            for (int j = 0; j < 8; j++) {
                mma16816(sacc[j], qh, bh[j]);
                mma16816(sacc[j], qh, bl[j]);
                mma16816(sacc[j], ql, bh[j]);
            }
        }

        // scale + causal mask + row max
        const int row0 = r0 + mrow, row1 = row0 + 8;
        float mx0 = -CUDART_INF_F, mx1 = -CUDART_INF_F;
        #pragma unroll
        for (int j = 0; j < 8; j++) {
            int c0 = j0 + j * 8 + t4 * 2, c1 = c0 + 1;
            sacc[j][0] = (c0 > row0) ? -CUDART_INF_F : sacc[j][0] * SCALE;
            sacc[j][1] = (c1 > row0) ? -CUDART_INF_F : sacc[j][1] * SCALE;
            sacc[j][2] = (c0 > row1) ? -CUDART_INF_F : sacc[j][2] * SCALE;
            sacc[j][3] = (c1 > row1) ? -CUDART_INF_F : sacc[j][3] * SCALE;
            mx0 = fmaxf(mx0, fmaxf(sacc[j][0], sacc[j][1]));
            mx1 = fmaxf(mx1, fmaxf(sacc[j][2], sacc[j][3]));
        }
        mx0 = fmaxf(mx0, __shfl_xor_sync(0xffffffffu, mx0, 1));
        mx0 = fmaxf(mx0, __shfl_xor_sync(0xffffffffu, mx0, 2));
        mx1 = fmaxf(mx1, __shfl_xor_sync(0xffffffffu, mx1, 1));
        mx1 = fmaxf(mx1, __shfl_xor_sync(0xffffffffu, mx1, 2));

        float mn0 = fmaxf(m0, mx0), mn1 = fmaxf(m1, mx1);
        float al0 = __expf(m0 - mn0), al1 = __expf(m1 - mn1);
        m0 = mn0; m1 = mn1;

        // exp + pack P to bf16 hi/lo fragments (registers only)
        float s0 = 0.0f, s1 = 0.0f;
        uint32_t ph0[8], ph1[8], pl0[8], pl1[8];
        #pragma unroll
        for (int j = 0; j < 8; j++) {
            float p00 = __expf(sacc[j][0] - mn0);
            float p01 = __expf(sacc[j][1] - mn0);
            float p10 = __expf(sacc[j][2] - mn1);
            float p11 = __expf(sacc[j][3] - mn1);
            s0 += p00 + p01;
            s1 += p10 + p11;
            split2(p00, p01, ph0[j], pl0[j]);
            split2(p10, p11, ph1[j], pl1[j]);
        }
        s0 += __shfl_xor_sync(0xffffffffu, s0, 1);
        s0 += __shfl_xor_sync(0xffffffffu, s0, 2);
        s1 += __shfl_xor_sync(0xffffffffu, s1, 1);
        s1 += __shfl_xor_sync(0xffffffffu, s1, 2);
        l0 = l0 * al0 + s0;
        l1 = l1 * al1 + s1;

        // rescale O accumulators
        #pragma unroll
        for (int nf = 0; nf < 16; nf++) {
            oacc[nf][0] *= al0; oacc[nf][1] *= al0;
            oacc[nf][2] *= al1; oacc[nf][3] *= al1;
        }

        // O += P V
        #pragma unroll
        for (int kk = 0; kk < 4; kk++) {
            uint32_t pah[4] = {ph0[2 * kk], ph1[2 * kk],
                               ph0[2 * kk + 1], ph1[2 * kk + 1]};
            uint32_t pal[4] = {pl0[2 * kk], pl1[2 * kk],
                               pl0[2 * kk + 1], pl1[2 * kk + 1]};
            int k = kk * 16;
            #pragma unroll
            for (int np = 0; np < 8; np++) {
                uint32_t off = (uint32_t)((np * 16 + b_r) * VS + k + b_c) * 2u;
                uint32_t vh4[4], vl4[4];
                ldm_x4(vh4, aVh + off);
                ldm_x4(vl4, aVl + off);
                mma16816(oacc[2 * np],     pah, vh4);
                mma16816(oacc[2 * np],     pah, vl4);
                mma16816(oacc[2 * np],     pal, vh4);
                mma16816(oacc[2 * np + 1], pah, vh4 + 2);
                mma16816(oacc[2 * np + 1], pah, vl4 + 2);
                mma16816(oacc[2 * np + 1], pal, vh4 + 2);
            }
        }
        __syncthreads();   // protect stage (itr&1) before reload at itr+2
    }

    // normalize + split + write (bf16 hi/lo, ready for O-projection)
    float inv0 = 1.0f / l0, inv1 = 1.0f / l1;
    #pragma unroll
    for (int nf = 0; nf < 16; nf++) {
        int col = h * HD + nf * 8 + t4 * 2;
        uint32_t hh, ll;
        size_t o0 = (size_t)(r0 + mrow) * HID + col;
        split2(oacc[nf][0] * inv0, oacc[nf][1] * inv0, hh, ll);
        *(uint32_t*)&Oh[o0] = hh;
        *(uint32_t*)&Ol[o0] = ll;
        size_t o1 = (size_t)(r0 + mrow + 8) * HID + col;
        split2(oacc[nf][2] * inv1, oacc[nf][3] * inv1, hh, ll);
        *(uint32_t*)&Oh[o1] = hh;
        *(uint32_t*)&Ol[o1] = ll;
    }
}

// ---------------- launcher ----------------------------------------------------
extern "C" void kernel_launch(void* const* d_in, const int* in_sizes, int n_in,
                              void* d_out, int out_size) {
    const float* hidden  = (const float*)d_in[0];
    const float* k_cache = (const float*)d_in[1];
    const float* v_cache = (const float*)d_in[2];
    const float* Wq      = (const float*)d_in[3];
    const float* Wo      = (const float*)d_in[4];
    const int*   pos     = (const int*)d_in[5];
    float* out = (float*)d_out;

    float *qbuf;
    __nv_bfloat16 *ah, *al, *bh, *bl, *kvh, *kvl, *vth, *vtl;
    cudaGetSymbolAddress((void**)&qbuf, g_Q);
    cudaGetSymbolAddress((void**)&ah, g_Ah);
    cudaGetSymbolAddress((void**)&al, g_Al);
    cudaGetSymbolAddress((void**)&bh, g_Bh);
    cudaGetSymbolAddress((void**)&bl, g_Bl);
    cudaGetSymbolAddress((void**)&kvh, g_Kh);
    cudaGetSymbolAddress((void**)&kvl, g_Kl);
    cudaGetSymbolAddress((void**)&vth, g_Vth);
    cudaGetSymbolAddress((void**)&vtl, g_Vtl);

    const int gemm_smem = 2 * 4 * 128 * SPAD * 2;   // 147456 B
    cudaFuncSetAttribute(gemm_mma, cudaFuncAttributeMaxDynamicSharedMemorySize,
                         gemm_smem);
    const int attn_smem = 2 * 128 * QS * 2 + 2 * (int)KV_STAGE;  // 212992 B
    cudaFuncSetAttribute(attn_mma, cudaFuncAttributeMaxDynamicSharedMemorySize,
                         attn_smem);

    dim3 gGemm(HID / 128, S_LEN / 128);             // (32, 16)
    dim3 gT(HID / 32, HID / 32);                    // (128, 128)
    dim3 gTV(S_LEN / 32, HD / 32, NKV);             // (64, 4, 8)
    dim3 bT(32, 8);
    int convBlocks  = (S_LEN * HID / 4) / 256;      // 8192
    int convBlocksK = (NKV * S_LEN * HD / 4) / 256; // 2048

    // 1) K pre-split
    conv_split_kernel<<<convBlocksK, 256>>>((const float4*)k_cache, (uint2*)kvh, (uint2*)kvl);
    // 2) V pre-split + transpose
    conv_split_TV_kernel<<<gTV, bT>>>(v_cache, vth, vtl);
    // 3) hidden split
    conv_split_kernel<<<convBlocks, 256>>>((const float4*)hidden, (uint2*)ah, (uint2*)al);
    // 4) Wq split+T
    conv_split_T_kernel<<<gT, bT>>>(Wq, bh, bl);
    // 5) Q projection
    gemm_mma<<<gGemm, 256, gemm_smem>>>(ah, al, bh, bl, qbuf);
    // 6) fused RoPE + split (g_Q -> ah/al)
    rope_split_kernel<<<(S_LEN * NH * 16) / 256, 256>>>(qbuf, pos, ah, al);
    // 7) flash attention; output pre-split into ah/al (in-place per-CTA slice)
    dim3 gAttn(S_LEN / 128, NH);
    attn_mma<<<gAttn, 256, attn_smem>>>(ah, al, kvh, kvl, vth, vtl, ah, al);
    // 8) Wo split+T
    conv_split_T_kernel<<<gT, bT>>>(Wo, bh, bl);
    // 9) O projection
    gemm_mma<<<gGemm, 256, gemm_smem>>>(ah, al, bh, bl, out);
}